// round 2
// baseline (speedup 1.0000x reference)
#include <cuda_runtime.h>
#include <math.h>

#define D 64
#define N_MAX 327680
#define S_MAX 16384

// ---- scratch (static device globals: allowed; no runtime allocation) ----
__device__ float g_h   [N_MAX * D];   // node hidden state
__device__ float g_m   [N_MAX * D];   // messages / hW2 reuse
__device__ float g_agg [N_MAX * D];   // aggregated messages
__device__ float g_vn  [S_MAX * D];
__device__ float g_vnW1[S_MAX * D];
__device__ float g_sg  [S_MAX * D];
__device__ float g_sh  [S_MAX * D];
__device__ int   g_last[S_MAX];
__device__ double g_acc[2];           // [0]=loss, [1]=sum of squares

__device__ __forceinline__ float sigmoidf_(float x) { return 1.f / (1.f + expf(-x)); }

// buffer selectors (resolved in device code; avoids cudaGetSymbolAddress)
__device__ __forceinline__ const float* sel_src(int s) {
    switch (s) {
        case 0: return g_h;
        case 1: return g_vn;
        case 2: return g_sg;
        default: return g_m;
    }
}
__device__ __forceinline__ float* sel_dst(int s) {
    switch (s) {
        case 0: return g_m;
        case 1: return g_vnW1;
        case 2: return g_sh;
        default: return g_h;
    }
}

// ---------------------------------------------------------------- gather
__global__ void gather_kernel(const float* __restrict__ item_emb,
                              const int* __restrict__ items, int N)
{
    int idx = blockIdx.x * blockDim.x + threadIdx.x;
    if (idx >= N * D) return;
    int n = idx >> 6, c = idx & 63;
    g_h[idx] = item_emb[(items[n] - 1) * D + c];
}

// ------------------------------------------------------- zero helpers
__global__ void zero_agg_kernel(int count)
{
    int i = blockIdx.x * blockDim.x + threadIdx.x;
    if (i < count) g_agg[i] = 0.f;
}
__global__ void zero_misc_kernel(int S)
{
    int i = blockIdx.x * blockDim.x + threadIdx.x;
    if (i < S * D) g_sg[i] = 0.f;
    if (i < S)     g_last[i] = 0;
    if (i < 2)     g_acc[i] = 0.0;
}

// ------------------------------------------------------------- GEMM 64
// C[n, 0..63] = sum_k A[n,k] * Beff[k,j]  (+bias, +=C optional)
// transB=0: Beff[k][j] = B[k*ldb + j]
// transB=1: Beff[k][j] = B[j*ldb + k]
__global__ void __launch_bounds__(256) gemm64(
    int Asel, const float* __restrict__ B,
    int Csel, int nrows, int ldb, int transB,
    const float* __restrict__ bias, int accum)
{
    const float* A = sel_src(Asel);
    float* C = sel_dst(Csel);

    __shared__ float sAt[64][68];  // [k][row]
    __shared__ float sB [64][68];  // [k][j]
    int tid = threadIdx.x;
    int rowBase = blockIdx.x * 64;

    for (int i = tid; i < 64 * 64; i += 256) {
        int r = i >> 6, k = i & 63;
        int gr = rowBase + r;
        sAt[k][r] = (gr < nrows) ? A[gr * 64 + k] : 0.f;
    }
    if (!transB) {
        for (int i = tid; i < 64 * 64; i += 256) {
            int k = i >> 6, j = i & 63;
            sB[k][j] = B[k * ldb + j];
        }
    } else {
        for (int i = tid; i < 64 * 64; i += 256) {
            int j = i >> 6, k = i & 63;
            sB[k][j] = B[j * ldb + k];
        }
    }
    __syncthreads();

    int r0 = (tid >> 4) * 4, c0 = (tid & 15) * 4;
    float acc[4][4] = {};
#pragma unroll
    for (int k = 0; k < 64; k++) {
        float4 a = *(const float4*)&sAt[k][r0];
        float4 b = *(const float4*)&sB[k][c0];
        float av[4] = {a.x, a.y, a.z, a.w};
        float bv[4] = {b.x, b.y, b.z, b.w};
#pragma unroll
        for (int i = 0; i < 4; i++)
#pragma unroll
            for (int j = 0; j < 4; j++)
                acc[i][j] = fmaf(av[i], bv[j], acc[i][j]);
    }

    float4 bb = make_float4(0.f, 0.f, 0.f, 0.f);
    if (bias) { bb.x = bias[c0]; bb.y = bias[c0 + 1]; bb.z = bias[c0 + 2]; bb.w = bias[c0 + 3]; }
#pragma unroll
    for (int i = 0; i < 4; i++) {
        int gr = rowBase + r0 + i;
        if (gr < nrows) {
            float* cp = C + gr * 64 + c0;
            float4 o;
            o.x = acc[i][0] + bb.x; o.y = acc[i][1] + bb.y;
            o.z = acc[i][2] + bb.z; o.w = acc[i][3] + bb.w;
            if (accum) {
                float4 p = *(const float4*)cp;
                o.x += p.x; o.y += p.y; o.z += p.z; o.w += p.w;
            }
            *(float4*)cp = o;
        }
    }
}

// ------------------------------------------------------------- scatter
__global__ void scatter_kernel(const int* __restrict__ src,
                               const int* __restrict__ dst, int E)
{
    int idx = blockIdx.x * blockDim.x + threadIdx.x;
    int e = idx >> 4;
    if (e >= E) return;
    int c = (idx & 15) << 2;
    int s = __ldg(&src[e]);
    int d = __ldg(&dst[e]);
    float4 v = *(const float4*)&g_m[s * 64 + c];
    float* p = &g_agg[d * 64 + c];
    atomicAdd(p + 0, v.x); atomicAdd(p + 1, v.y);
    atomicAdd(p + 2, v.z); atomicAdd(p + 3, v.w);
}

// ------------------------------------------------------- fused GRU cell
// Computes gi = agg@W_ih^T, gh = h@W_hh^T and the GRU update in one pass,
// in-place on g_h. Block = 64 nodes, 512 threads, each thread: 2 nodes x 4 j
// x 6 accumulators. Dynamic smem: transposed agg/h tiles + transposed weights.
#define GRU_SMEM ((2 * 64 * 68 + 2 * 64 * 196) * 4)
__global__ void __launch_bounds__(512) gru_fused(
    const float* __restrict__ W_ih, const float* __restrict__ W_hh,
    const float* __restrict__ b_ih, const float* __restrict__ b_hh,
    int nrows, int do_relu)
{
    extern __shared__ float sm[];
    float* sA  = sm;                  // [64][68] : sA[k*68 + node] = agg[node][k]
    float* sH  = sm + 64 * 68;        // [64][68]
    float* sWi = sm + 2 * 64 * 68;    // [64][196]: sWi[k*196 + j] = W_ih[j][k], j<192
    float* sWh = sWi + 64 * 196;

    int tid = threadIdx.x;
    int rowBase = blockIdx.x * 64;

    for (int i = tid; i < 64 * 64; i += 512) {
        int r = i >> 6, k = i & 63;
        int gr = rowBase + r;
        float av = 0.f, hv = 0.f;
        if (gr < nrows) { av = g_agg[gr * 64 + k]; hv = g_h[gr * 64 + k]; }
        sA[k * 68 + r] = av;
        sH[k * 68 + r] = hv;
    }
    for (int i = tid; i < 192 * 64; i += 512) {
        int j = i >> 6, k = i & 63;
        sWi[k * 196 + j] = W_ih[i];
        sWh[k * 196 + j] = W_hh[i];
    }
    __syncthreads();

    int n0 = (tid >> 4) * 2;   // node pair
    int j0 = (tid & 15) * 4;   // 4 output columns

    float ir[2][4] = {}, iz[2][4] = {}, inn[2][4] = {};
    float hr[2][4] = {}, hz[2][4] = {}, hn[2][4] = {};

#pragma unroll 8
    for (int k = 0; k < 64; k++) {
        float2 a  = *(const float2*)&sA[k * 68 + n0];
        float2 hh = *(const float2*)&sH[k * 68 + n0];
        const float* wik = &sWi[k * 196];
        const float* whk = &sWh[k * 196];
        float4 wir = *(const float4*)&wik[j0];
        float4 wiz = *(const float4*)&wik[64 + j0];
        float4 win = *(const float4*)&wik[128 + j0];
        float4 whr = *(const float4*)&whk[j0];
        float4 whz = *(const float4*)&whk[64 + j0];
        float4 whn = *(const float4*)&whk[128 + j0];
        float aa[2]  = {a.x, a.y};
        float hv2[2] = {hh.x, hh.y};
        float wirv[4] = {wir.x, wir.y, wir.z, wir.w};
        float wizv[4] = {wiz.x, wiz.y, wiz.z, wiz.w};
        float winv[4] = {win.x, win.y, win.z, win.w};
        float whrv[4] = {whr.x, whr.y, whr.z, whr.w};
        float whzv[4] = {whz.x, whz.y, whz.z, whz.w};
        float whnv[4] = {whn.x, whn.y, whn.z, whn.w};
#pragma unroll
        for (int t = 0; t < 2; t++) {
#pragma unroll
            for (int q = 0; q < 4; q++) {
                ir[t][q]  = fmaf(aa[t],  wirv[q], ir[t][q]);
                iz[t][q]  = fmaf(aa[t],  wizv[q], iz[t][q]);
                inn[t][q] = fmaf(aa[t],  winv[q], inn[t][q]);
                hr[t][q]  = fmaf(hv2[t], whrv[q], hr[t][q]);
                hz[t][q]  = fmaf(hv2[t], whzv[q], hz[t][q]);
                hn[t][q]  = fmaf(hv2[t], whnv[q], hn[t][q]);
            }
        }
    }

#pragma unroll
    for (int t = 0; t < 2; t++) {
        int gr = rowBase + n0 + t;
        if (gr >= nrows) continue;
        float ov[4];
#pragma unroll
        for (int q = 0; q < 4; q++) {
            int j = j0 + q;
            float irv = ir[t][q]  + b_ih[j];
            float izv = iz[t][q]  + b_ih[64 + j];
            float inv = inn[t][q] + b_ih[128 + j];
            float hrv = hr[t][q]  + b_hh[j];
            float hzv = hz[t][q]  + b_hh[64 + j];
            float hnv = hn[t][q]  + b_hh[128 + j];
            float r = sigmoidf_(irv + hrv);
            float z = sigmoidf_(izv + hzv);
            float nv = tanhf(inv + r * hnv);
            float ho = sH[j * 68 + n0 + t];    // old h[gr][j] from transposed tile
            float val = (1.f - z) * nv + z * ho;
            if (do_relu) val = fmaxf(val, 0.f);
            ov[q] = val;
        }
        *(float4*)&g_h[gr * 64 + j0] = make_float4(ov[0], ov[1], ov[2], ov[3]);
    }
}

// ----------------------------------------------------- last-node / v_n
__global__ void lastmax_kernel(const int* __restrict__ batch, int N)
{
    int idx = blockIdx.x * blockDim.x + threadIdx.x;
    if (idx >= N) return;
    atomicMax(&g_last[batch[idx]], idx);
}
__global__ void vngather_kernel(int S)
{
    int idx = blockIdx.x * blockDim.x + threadIdx.x;
    if (idx >= S * D) return;
    int s = idx >> 6;
    g_vn[idx] = g_h[g_last[s] * 64 + (idx & 63)];
}

// --------------------------------------------------- attention / gate
// gate = sigmoid(vnW1[batch] + hW2 + b1 + b2); alpha = gate.qw + qb;
// sg[batch] += alpha * h.   One warp per node, 2 columns per lane.
__global__ void gate_kernel(const int* __restrict__ batch,
                            const float* __restrict__ b1, const float* __restrict__ b2,
                            const float* __restrict__ qw, const float* __restrict__ qb,
                            int N)
{
    int gidx = blockIdx.x * blockDim.x + threadIdx.x;
    int n = gidx >> 5;
    if (n >= N) return;
    int lane = gidx & 31;
    int b = batch[n];
    int j0 = lane, j1 = lane + 32;

    float x0 = g_vnW1[b * 64 + j0] + g_m[n * 64 + j0] + b1[j0] + b2[j0];
    float x1 = g_vnW1[b * 64 + j1] + g_m[n * 64 + j1] + b1[j1] + b2[j1];
    float gv0 = sigmoidf_(x0), gv1 = sigmoidf_(x1);
    float hv0 = g_h[n * 64 + j0], hv1 = g_h[n * 64 + j1];
    float alpha = fmaf(gv0, qw[j0], gv1 * qw[j1]);
#pragma unroll
    for (int o = 16; o; o >>= 1) alpha += __shfl_xor_sync(0xffffffffu, alpha, o);
    alpha += qb[0];
    atomicAdd(&g_sg[b * 64 + j0], alpha * hv0);
    atomicAdd(&g_sg[b * 64 + j1], alpha * hv1);
}

// ------------------------------------------------------------ BPR loss
__global__ void loss_kernel(const float* __restrict__ item_emb,
                            const int* __restrict__ pos, const int* __restrict__ neg,
                            int S)
{
    int gidx = blockIdx.x * blockDim.x + threadIdx.x;
    int s = gidx >> 5;
    if (s >= S) return;
    int lane = gidx & 31;
    int ip = pos[s], in2 = neg[s];
    float pp = 0.f, np = 0.f, rg = 0.f;
#pragma unroll
    for (int t = 0; t < 2; t++) {
        int j = lane + t * 32;
        float sv = g_sh[s * 64 + j];
        float pe = item_emb[ip * 64 + j];
        float ne = item_emb[in2 * 64 + j];
        pp = fmaf(sv, pe, pp);
        np = fmaf(sv, ne, np);
        rg += sv * sv + pe * pe + ne * ne;
    }
#pragma unroll
    for (int o = 16; o; o >>= 1) {
        pp += __shfl_xor_sync(0xffffffffu, pp, o);
        np += __shfl_xor_sync(0xffffffffu, np, o);
        rg += __shfl_xor_sync(0xffffffffu, rg, o);
    }
    if (lane == 0) {
        float x = pp - np;
        float lsm = (x > 0.f) ? log1pf(expf(-x)) : (-x + log1pf(expf(x)));
        atomicAdd(&g_acc[0], (double)lsm);
        atomicAdd(&g_acc[1], (double)rg);
    }
}

__global__ void finalize_kernel(float* out, int out_size)
{
    double loss = g_acc[0];
    double nr = g_acc[1] * 1e-5;
    float t = (float)(loss + nr), l = (float)loss, r = (float)nr;
    if (out_size > 0) out[0] = t;
    if (out_size > 1) out[1] = l;
    if (out_size > 2) out[2] = r;
    if (out_size > 3) out[3] = r;
    if (out_size > 4) out[4] = r;
}

// ---------------------------------------------------------------- host
extern "C" void kernel_launch(void* const* d_in, const int* in_sizes, int n_in,
                              void* d_out, int out_size)
{
    const float* item_emb = (const float*)d_in[0];
    const float* ggc      = (const float*)d_in[1];
    const float* W_ih     = (const float*)d_in[2];
    const float* b_ih     = (const float*)d_in[3];
    const float* W_hh     = (const float*)d_in[4];
    const float* b_hh     = (const float*)d_in[5];
    const float* W1       = (const float*)d_in[6];
    const float* b1       = (const float*)d_in[7];
    const float* W2       = (const float*)d_in[8];
    const float* b2       = (const float*)d_in[9];
    const float* qw       = (const float*)d_in[10];
    const float* qb       = (const float*)d_in[11];
    const float* W3       = (const float*)d_in[12];
    const float* b3       = (const float*)d_in[13];
    const int* node_items = (const int*)d_in[14];
    const int* edge_index = (const int*)d_in[15];
    const int* batch      = (const int*)d_in[16];
    const int* pos        = (const int*)d_in[17];
    const int* neg        = (const int*)d_in[18];

    int N = in_sizes[14];
    int E = in_sizes[15] / 2;
    int S = in_sizes[17];
    float* out = (float*)d_out;

    cudaFuncSetAttribute(gru_fused, cudaFuncAttributeMaxDynamicSharedMemorySize, GRU_SMEM);

    const int* src = edge_index;
    const int* dst = edge_index + E;

    zero_misc_kernel<<<(S * D + 255) / 256, 256>>>(S);
    gather_kernel<<<(N * D + 255) / 256, 256>>>(item_emb, node_items, N);

    for (int layer = 0; layer < 2; layer++) {
        // m = h @ ggc_weight[layer]   (Asel=0: g_h, Csel=0: g_m)
        gemm64<<<(N + 63) / 64, 256>>>(0, ggc + layer * 64 * 64, 0, N, 64, 0, nullptr, 0);
        zero_agg_kernel<<<(N * D + 255) / 256, 256>>>(N * D);
        scatter_kernel<<<(E * 16 + 255) / 256, 256>>>(src, dst, E);
        gru_fused<<<(N + 63) / 64, 512, GRU_SMEM>>>(W_ih, W_hh, b_ih, b_hh, N, layer == 1);
    }

    lastmax_kernel<<<(N + 255) / 256, 256>>>(batch, N);
    vngather_kernel<<<(S * D + 255) / 256, 256>>>(S);

    // vnW1 = v_n @ W1^T (Asel=1 -> Csel=1) ;  hW2 = h @ W2^T (Asel=0 -> g_m)
    gemm64<<<(S + 63) / 64, 256>>>(1, W1, 1, S, 64, 1, nullptr, 0);
    gemm64<<<(N + 63) / 64, 256>>>(0, W2, 0, N, 64, 1, nullptr, 0);
    gate_kernel<<<(N * 32 + 255) / 256, 256>>>(batch, b1, b2, qw, qb, N);

    // s_h = [v_n | s_g] @ W3^T + b3   (split K: W3[:, :64] then W3[:, 64:])
    gemm64<<<(S + 63) / 64, 256>>>(1, W3,      2, S, 128, 1, nullptr, 0);
    gemm64<<<(S + 63) / 64, 256>>>(2, W3 + 64, 2, S, 128, 1, b3, 1);

    loss_kernel<<<(S * 32 + 255) / 256, 256>>>(item_emb, pos, neg, S);
    finalize_kernel<<<1, 1>>>(out, out_size);
}

// round 3
// speedup vs baseline: 1.2889x; 1.2889x over previous
#include <cuda_runtime.h>
#include <math.h>
#include <stdint.h>

#define D 64
#define N_MAX 327680
#define S_MAX 16384

// ---- scratch (static device globals) ----
__device__ float g_h   [N_MAX * D];
__device__ float g_m   [N_MAX * D];
__device__ float g_agg [N_MAX * D];
__device__ float g_vn  [S_MAX * D];
__device__ float g_vnW1[S_MAX * D];
__device__ float g_sg  [S_MAX * D];
__device__ float g_sh  [S_MAX * D];
__device__ int   g_last[S_MAX];
__device__ double g_acc[2];

__device__ __forceinline__ float sigmoidf_(float x) { return 1.f / (1.f + expf(-x)); }

__device__ __forceinline__ uint32_t f2tf32(float v) {
    uint32_t o;
    asm("cvt.rna.tf32.f32 %0, %1;" : "=r"(o) : "f"(v));
    return o;
}

// buffer selectors (device-side; no cudaGetSymbolAddress)
__device__ __forceinline__ const float* sel_src(int s) {
    switch (s) {
        case 0: return g_h;
        case 1: return g_vn;
        case 2: return g_sg;
        default: return g_m;
    }
}
__device__ __forceinline__ float* sel_dst(int s) {
    switch (s) {
        case 0: return g_m;
        case 1: return g_vnW1;
        case 2: return g_sh;
        default: return g_h;
    }
}

// ---------------------------------------------------------------- gather
__global__ void gather_kernel(const float* __restrict__ item_emb,
                              const int* __restrict__ items, int N)
{
    int idx = blockIdx.x * blockDim.x + threadIdx.x;
    if (idx >= N * D) return;
    int n = idx >> 6, c = idx & 63;
    g_h[idx] = item_emb[(items[n] - 1) * D + c];
}

// ------------------------------------------------------- zero helpers
__global__ void zero_agg_kernel(int count4)   // count4 = N*D/4
{
    int i = blockIdx.x * blockDim.x + threadIdx.x;
    if (i < count4) ((float4*)g_agg)[i] = make_float4(0.f, 0.f, 0.f, 0.f);
}
__global__ void zero_misc_kernel(int S)
{
    int i = blockIdx.x * blockDim.x + threadIdx.x;
    if (i < S * D) g_sg[i] = 0.f;
    if (i < S)     g_last[i] = 0;
    if (i < 2)     g_acc[i] = 0.0;
}

// ------------------------------------------------------------- GEMM 64 (fp32)
__global__ void __launch_bounds__(256) gemm64(
    int Asel, const float* __restrict__ B,
    int Csel, int nrows, int ldb, int transB,
    const float* __restrict__ bias, int accum)
{
    const float* A = sel_src(Asel);
    float* C = sel_dst(Csel);

    __shared__ float sAt[64][68];
    __shared__ float sB [64][68];
    int tid = threadIdx.x;
    int rowBase = blockIdx.x * 64;

    for (int i = tid; i < 64 * 64; i += 256) {
        int r = i >> 6, k = i & 63;
        int gr = rowBase + r;
        sAt[k][r] = (gr < nrows) ? A[gr * 64 + k] : 0.f;
    }
    if (!transB) {
        for (int i = tid; i < 64 * 64; i += 256) {
            int k = i >> 6, j = i & 63;
            sB[k][j] = B[k * ldb + j];
        }
    } else {
        for (int i = tid; i < 64 * 64; i += 256) {
            int j = i >> 6, k = i & 63;
            sB[k][j] = B[j * ldb + k];
        }
    }
    __syncthreads();

    int r0 = (tid >> 4) * 4, c0 = (tid & 15) * 4;
    float acc[4][4] = {};
#pragma unroll
    for (int k = 0; k < 64; k++) {
        float4 a = *(const float4*)&sAt[k][r0];
        float4 b = *(const float4*)&sB[k][c0];
        float av[4] = {a.x, a.y, a.z, a.w};
        float bv[4] = {b.x, b.y, b.z, b.w};
#pragma unroll
        for (int i = 0; i < 4; i++)
#pragma unroll
            for (int j = 0; j < 4; j++)
                acc[i][j] = fmaf(av[i], bv[j], acc[i][j]);
    }

    float4 bb = make_float4(0.f, 0.f, 0.f, 0.f);
    if (bias) { bb.x = bias[c0]; bb.y = bias[c0 + 1]; bb.z = bias[c0 + 2]; bb.w = bias[c0 + 3]; }
#pragma unroll
    for (int i = 0; i < 4; i++) {
        int gr = rowBase + r0 + i;
        if (gr < nrows) {
            float* cp = C + gr * 64 + c0;
            float4 o;
            o.x = acc[i][0] + bb.x; o.y = acc[i][1] + bb.y;
            o.z = acc[i][2] + bb.z; o.w = acc[i][3] + bb.w;
            if (accum) {
                float4 p = *(const float4*)cp;
                o.x += p.x; o.y += p.y; o.z += p.z; o.w += p.w;
            }
            *(float4*)cp = o;
        }
    }
}

// ------------------------------------------------------------- scatter
__global__ void scatter_kernel(const int* __restrict__ src,
                               const int* __restrict__ dst, int E)
{
    int idx = blockIdx.x * blockDim.x + threadIdx.x;
    int e = idx >> 4;
    if (e >= E) return;
    int c = (idx & 15) << 2;
    int s = __ldg(&src[e]);
    int d = __ldg(&dst[e]);
    float4 v = *(const float4*)&g_m[s * 64 + c];
    float* p = &g_agg[d * 64 + c];
    atomicAdd(p + 0, v.x); atomicAdd(p + 1, v.y);
    atomicAdd(p + 2, v.z); atomicAdd(p + 3, v.w);
}

// ----------------------------------------------- fused GRU via tf32 mma.sync
// Per CTA: rows [rowBase, rowBase+128). One M=128,N=256,K=128 tf32 GEMM:
//   A[r][k]   = k<64 ? agg[r][k] : h[r][k-64]
//   B cols:   [0,64)  r-gate : W_ih[j] | W_hh[j]        (K-concat -> i_r+h_r)
//             [64,128) z-gate: W_ih[64+j] | W_hh[64+j]  (-> i_z+h_z)
//             [128,192) i_n  : W_ih[128+j] | 0
//             [192,256) h_n  : 0 | W_hh[128+j]
// Epilogue: stage C in smem (reuse B region), apply GRU with exact fp32 h_old.
#define AP 132
#define BP 132
#define CP 260
#define GRUM_SMEM ((128 * AP + 256 * BP) * 4)

__device__ __forceinline__ void mma_tf32(float d[4], const uint32_t a[4],
                                         uint32_t b0, uint32_t b1)
{
    asm volatile(
        "mma.sync.aligned.m16n8k8.row.col.f32.tf32.tf32.f32 "
        "{%0,%1,%2,%3}, {%4,%5,%6,%7}, {%8,%9}, {%0,%1,%2,%3};"
        : "+f"(d[0]), "+f"(d[1]), "+f"(d[2]), "+f"(d[3])
        : "r"(a[0]), "r"(a[1]), "r"(a[2]), "r"(a[3]), "r"(b0), "r"(b1));
}

__global__ void __launch_bounds__(512, 1) gru_mma(
    const float* __restrict__ W_ih, const float* __restrict__ W_hh,
    const float* __restrict__ b_ih, const float* __restrict__ b_hh,
    int nrows, int do_relu)
{
    extern __shared__ uint32_t sm[];
    uint32_t* sA = sm;              // [128][AP]
    uint32_t* sB = sm + 128 * AP;   // [256][BP]

    int tid = threadIdx.x;
    int lane = tid & 31;
    int warp = tid >> 5;
    int rowBase = blockIdx.x * 128;

    // ---- fill A (tf32-rounded) ----
    for (int i = tid; i < 128 * 128; i += 512) {
        int r = i >> 7, k = i & 127;
        int gr = rowBase + r;
        float v = (k < 64) ? g_agg[gr * 64 + k] : g_h[gr * 64 + (k - 64)];
        sA[r * AP + k] = f2tf32(v);
    }
    // ---- fill B (tf32-rounded, gate-blocked) ----
    for (int i = tid; i < 256 * 128; i += 512) {
        int c = i >> 7, k = i & 127;
        int j = c & 63, g = c >> 6;
        float v;
        if (g == 0)      v = (k < 64) ? W_ih[j * 64 + k]          : W_hh[j * 64 + (k - 64)];
        else if (g == 1) v = (k < 64) ? W_ih[(64 + j) * 64 + k]   : W_hh[(64 + j) * 64 + (k - 64)];
        else if (g == 2) v = (k < 64) ? W_ih[(128 + j) * 64 + k]  : 0.f;
        else             v = (k < 64) ? 0.f                        : W_hh[(128 + j) * 64 + (k - 64)];
        sB[c * BP + k] = f2tf32(v);
    }
    __syncthreads();

    // ---- MMA mainloop: warp grid 4(M) x 4(N); warp tile 32x64 ----
    int rowW = (warp >> 2) * 32;
    int colW = (warp & 3) * 64;
    float acc[2][8][4];
#pragma unroll
    for (int mt = 0; mt < 2; mt++)
#pragma unroll
        for (int nt = 0; nt < 8; nt++)
#pragma unroll
            for (int q = 0; q < 4; q++) acc[mt][nt][q] = 0.f;

    int lr = lane >> 2, lk = lane & 3;
#pragma unroll
    for (int k0 = 0; k0 < 128; k0 += 8) {
        uint32_t a[2][4];
#pragma unroll
        for (int mt = 0; mt < 2; mt++) {
            int r = rowW + mt * 16 + lr;
            a[mt][0] = sA[r * AP + k0 + lk];
            a[mt][1] = sA[(r + 8) * AP + k0 + lk];
            a[mt][2] = sA[r * AP + k0 + lk + 4];
            a[mt][3] = sA[(r + 8) * AP + k0 + lk + 4];
        }
#pragma unroll
        for (int nt = 0; nt < 8; nt++) {
            int cc = colW + nt * 8 + lr;
            uint32_t b0 = sB[cc * BP + k0 + lk];
            uint32_t b1 = sB[cc * BP + k0 + lk + 4];
            mma_tf32(acc[0][nt], a[0], b0, b1);
            mma_tf32(acc[1][nt], a[1], b0, b1);
        }
    }

    // ---- stage C into smem (reuse B region: 128*260 <= 256*132) ----
    __syncthreads();
    float* sC = (float*)sB;
#pragma unroll
    for (int mt = 0; mt < 2; mt++) {
#pragma unroll
        for (int nt = 0; nt < 8; nt++) {
            int r = rowW + mt * 16 + lr;
            int cc = colW + nt * 8 + (lk << 1);
            *(float2*)&sC[r * CP + cc]       = make_float2(acc[mt][nt][0], acc[mt][nt][1]);
            *(float2*)&sC[(r + 8) * CP + cc] = make_float2(acc[mt][nt][2], acc[mt][nt][3]);
        }
    }
    __syncthreads();

    // ---- GRU elementwise epilogue ----
    for (int i = tid; i < 128 * 64; i += 512) {
        int r = i >> 6, j = i & 63;
        int gr = rowBase + r;
        if (gr >= nrows) continue;
        float rzr = sC[r * CP + j]        + __ldg(&b_ih[j])       + __ldg(&b_hh[j]);
        float rzz = sC[r * CP + 64 + j]   + __ldg(&b_ih[64 + j])  + __ldg(&b_hh[64 + j]);
        float i_n = sC[r * CP + 128 + j]  + __ldg(&b_ih[128 + j]);
        float h_n = sC[r * CP + 192 + j]  + __ldg(&b_hh[128 + j]);
        float rr = sigmoidf_(rzr);
        float zz = sigmoidf_(rzz);
        float nn = tanhf(i_n + rr * h_n);
        float ho = g_h[gr * 64 + j];      // exact fp32 h_old
        float val = (1.f - zz) * nn + zz * ho;
        if (do_relu) val = fmaxf(val, 0.f);
        g_h[gr * 64 + j] = val;
    }
}

// ----------------------------------------------------- last-node / v_n
__global__ void lastmax_kernel(const int* __restrict__ batch, int N)
{
    int idx = blockIdx.x * blockDim.x + threadIdx.x;
    if (idx >= N) return;
    atomicMax(&g_last[batch[idx]], idx);
}
__global__ void vngather_kernel(int S)
{
    int idx = blockIdx.x * blockDim.x + threadIdx.x;
    if (idx >= S * D) return;
    int s = idx >> 6;
    g_vn[idx] = g_h[g_last[s] * 64 + (idx & 63)];
}

// --------------------------------------------------- attention / gate
__global__ void gate_kernel(const int* __restrict__ batch,
                            const float* __restrict__ b1, const float* __restrict__ b2,
                            const float* __restrict__ qw, const float* __restrict__ qb,
                            int N)
{
    int gidx = blockIdx.x * blockDim.x + threadIdx.x;
    int n = gidx >> 5;
    if (n >= N) return;
    int lane = gidx & 31;
    int b = batch[n];
    int j0 = lane, j1 = lane + 32;

    float x0 = g_vnW1[b * 64 + j0] + g_m[n * 64 + j0] + b1[j0] + b2[j0];
    float x1 = g_vnW1[b * 64 + j1] + g_m[n * 64 + j1] + b1[j1] + b2[j1];
    float gv0 = sigmoidf_(x0), gv1 = sigmoidf_(x1);
    float hv0 = g_h[n * 64 + j0], hv1 = g_h[n * 64 + j1];
    float alpha = fmaf(gv0, qw[j0], gv1 * qw[j1]);
#pragma unroll
    for (int o = 16; o; o >>= 1) alpha += __shfl_xor_sync(0xffffffffu, alpha, o);
    alpha += qb[0];
    atomicAdd(&g_sg[b * 64 + j0], alpha * hv0);
    atomicAdd(&g_sg[b * 64 + j1], alpha * hv1);
}

// ------------------------------------------------------------ BPR loss
__global__ void loss_kernel(const float* __restrict__ item_emb,
                            const int* __restrict__ pos, const int* __restrict__ neg,
                            int S)
{
    int gidx = blockIdx.x * blockDim.x + threadIdx.x;
    int s = gidx >> 5;
    if (s >= S) return;
    int lane = gidx & 31;
    int ip = pos[s], in2 = neg[s];
    float pp = 0.f, np = 0.f, rg = 0.f;
#pragma unroll
    for (int t = 0; t < 2; t++) {
        int j = lane + t * 32;
        float sv = g_sh[s * 64 + j];
        float pe = item_emb[ip * 64 + j];
        float ne = item_emb[in2 * 64 + j];
        pp = fmaf(sv, pe, pp);
        np = fmaf(sv, ne, np);
        rg += sv * sv + pe * pe + ne * ne;
    }
#pragma unroll
    for (int o = 16; o; o >>= 1) {
        pp += __shfl_xor_sync(0xffffffffu, pp, o);
        np += __shfl_xor_sync(0xffffffffu, np, o);
        rg += __shfl_xor_sync(0xffffffffu, rg, o);
    }
    if (lane == 0) {
        float x = pp - np;
        float lsm = (x > 0.f) ? log1pf(expf(-x)) : (-x + log1pf(expf(x)));
        atomicAdd(&g_acc[0], (double)lsm);
        atomicAdd(&g_acc[1], (double)rg);
    }
}

__global__ void finalize_kernel(float* out, int out_size)
{
    double loss = g_acc[0];
    double nr = g_acc[1] * 1e-5;
    float t = (float)(loss + nr), l = (float)loss, r = (float)nr;
    if (out_size > 0) out[0] = t;
    if (out_size > 1) out[1] = l;
    if (out_size > 2) out[2] = r;
    if (out_size > 3) out[3] = r;
    if (out_size > 4) out[4] = r;
}

// ---------------------------------------------------------------- host
extern "C" void kernel_launch(void* const* d_in, const int* in_sizes, int n_in,
                              void* d_out, int out_size)
{
    const float* item_emb = (const float*)d_in[0];
    const float* ggc      = (const float*)d_in[1];
    const float* W_ih     = (const float*)d_in[2];
    const float* b_ih     = (const float*)d_in[3];
    const float* W_hh     = (const float*)d_in[4];
    const float* b_hh     = (const float*)d_in[5];
    const float* W1       = (const float*)d_in[6];
    const float* b1       = (const float*)d_in[7];
    const float* W2       = (const float*)d_in[8];
    const float* b2       = (const float*)d_in[9];
    const float* qw       = (const float*)d_in[10];
    const float* qb       = (const float*)d_in[11];
    const float* W3       = (const float*)d_in[12];
    const float* b3       = (const float*)d_in[13];
    const int* node_items = (const int*)d_in[14];
    const int* edge_index = (const int*)d_in[15];
    const int* batch      = (const int*)d_in[16];
    const int* pos        = (const int*)d_in[17];
    const int* neg        = (const int*)d_in[18];

    int N = in_sizes[14];
    int E = in_sizes[15] / 2;
    int S = in_sizes[17];
    float* out = (float*)d_out;

    cudaFuncSetAttribute(gru_mma, cudaFuncAttributeMaxDynamicSharedMemorySize, GRUM_SMEM);

    const int* src = edge_index;
    const int* dst = edge_index + E;

    zero_misc_kernel<<<(S * D + 255) / 256, 256>>>(S);
    gather_kernel<<<(N * D + 255) / 256, 256>>>(item_emb, node_items, N);

    for (int layer = 0; layer < 2; layer++) {
        gemm64<<<(N + 63) / 64, 256>>>(0, ggc + layer * 64 * 64, 0, N, 64, 0, nullptr, 0);
        zero_agg_kernel<<<(N * D / 4 + 255) / 256, 256>>>(N * D / 4);
        scatter_kernel<<<(E * 16 + 255) / 256, 256>>>(src, dst, E);
        gru_mma<<<(N + 127) / 128, 512, GRUM_SMEM>>>(W_ih, W_hh, b_ih, b_hh, N, layer == 1);
    }

    lastmax_kernel<<<(N + 255) / 256, 256>>>(batch, N);
    vngather_kernel<<<(S * D + 255) / 256, 256>>>(S);

    gemm64<<<(S + 63) / 64, 256>>>(1, W1, 1, S, 64, 1, nullptr, 0);
    gemm64<<<(N + 63) / 64, 256>>>(0, W2, 0, N, 64, 1, nullptr, 0);
    gate_kernel<<<(N * 32 + 255) / 256, 256>>>(batch, b1, b2, qw, qb, N);

    gemm64<<<(S + 63) / 64, 256>>>(1, W3,      2, S, 128, 1, nullptr, 0);
    gemm64<<<(S + 63) / 64, 256>>>(2, W3 + 64, 2, S, 128, 1, b3, 1);

    loss_kernel<<<(S * 32 + 255) / 256, 256>>>(item_emb, pos, neg, S);
    finalize_kernel<<<1, 1>>>(out, out_size);
}

// round 4
// speedup vs baseline: 1.8796x; 1.4583x over previous
#include <cuda_runtime.h>
#include <math.h>
#include <stdint.h>

#define D 64
#define N_MAX 327680
#define S_MAX 16384

// ---- scratch (static device globals) ----
__device__ float g_h   [N_MAX * D];
__device__ float g_m   [N_MAX * D];
__device__ float g_agg [N_MAX * D];
__device__ float g_vn  [S_MAX * D];
__device__ float g_vnW1[S_MAX * D];
__device__ float g_sg  [S_MAX * D];
__device__ float g_sh  [S_MAX * D];
__device__ int   g_last[S_MAX];
__device__ double g_acc[2];
// prepacked tf32 weights ([col][k] layouts matching smem B tiles)
__device__ uint32_t g_gruB[256 * 128];
__device__ uint32_t g_msgB[2 * 64 * 64];
__device__ uint32_t g_w2B [64 * 64];

__device__ __forceinline__ float sigmoidf_(float x) { return 1.f / (1.f + expf(-x)); }

__device__ __forceinline__ uint32_t f2tf32(float v) {
    uint32_t o;
    asm("cvt.rna.tf32.f32 %0, %1;" : "=r"(o) : "f"(v));
    return o;
}

__device__ __forceinline__ void mma_tf32(float d[4], const uint32_t a[4],
                                         uint32_t b0, uint32_t b1)
{
    asm volatile(
        "mma.sync.aligned.m16n8k8.row.col.f32.tf32.tf32.f32 "
        "{%0,%1,%2,%3}, {%4,%5,%6,%7}, {%8,%9}, {%0,%1,%2,%3};"
        : "+f"(d[0]), "+f"(d[1]), "+f"(d[2]), "+f"(d[3])
        : "r"(a[0]), "r"(a[1]), "r"(a[2]), "r"(a[3]), "r"(b0), "r"(b1));
}

// buffer selectors for the small fp32 gemm (device-side)
__device__ __forceinline__ const float* sel_src(int s) {
    switch (s) {
        case 1: return g_vn;
        case 2: return g_sg;
        default: return g_h;
    }
}
__device__ __forceinline__ float* sel_dst(int s) {
    switch (s) {
        case 1: return g_vnW1;
        case 2: return g_sh;
        default: return g_m;
    }
}

// ------------------------------------------------ weight prepack (tf32)
// g_gruB: c in [0,256): j=c&63, g=c>>6; k in [0,128)
//   g0: W_ih[j]|W_hh[j]  g1: W_ih[64+j]|W_hh[64+j]  g2: W_ih[128+j]|0  g3: 0|W_hh[128+j]
// g_msgB[layer][j][k] = ggc[layer][k][j]      (Beff[k][j] for m = h @ ggc)
// g_w2B[j][k]         = W2[j][k]              (Beff[k][j] for h @ W2^T)
__global__ void prepack_kernel(const float* __restrict__ W_ih,
                               const float* __restrict__ W_hh,
                               const float* __restrict__ ggc,
                               const float* __restrict__ W2)
{
    int idx = blockIdx.x * blockDim.x + threadIdx.x;
    if (idx < 256 * 128) {
        int c = idx >> 7, k = idx & 127;
        int j = c & 63, g = c >> 6;
        float v;
        if (g == 0)      v = (k < 64) ? W_ih[j * 64 + k]         : W_hh[j * 64 + (k - 64)];
        else if (g == 1) v = (k < 64) ? W_ih[(64 + j) * 64 + k]  : W_hh[(64 + j) * 64 + (k - 64)];
        else if (g == 2) v = (k < 64) ? W_ih[(128 + j) * 64 + k] : 0.f;
        else             v = (k < 64) ? 0.f                       : W_hh[(128 + j) * 64 + (k - 64)];
        g_gruB[idx] = f2tf32(v);
    } else if (idx < 256 * 128 + 2 * 4096) {
        int t = idx - 256 * 128;
        int layer = t >> 12, r = t & 4095;
        int j = r >> 6, k = r & 63;
        g_msgB[t] = f2tf32(ggc[layer * 4096 + k * 64 + j]);
    } else if (idx < 256 * 128 + 2 * 4096 + 4096) {
        int t = idx - (256 * 128 + 2 * 4096);
        g_w2B[t] = f2tf32(W2[t]);   // W2 row-major [j][k] already
    }
}

// ---------------------------------------------------------------- gather
__global__ void gather_kernel(const float* __restrict__ item_emb,
                              const int* __restrict__ items, int N)
{
    int idx = blockIdx.x * blockDim.x + threadIdx.x;
    if (idx >= N * D) return;
    int n = idx >> 6, c = idx & 63;
    g_h[idx] = item_emb[(items[n] - 1) * D + c];
}

// ------------------------------------------------------- zero helpers
__global__ void zero_agg_kernel(int count4)
{
    int i = blockIdx.x * blockDim.x + threadIdx.x;
    if (i < count4) ((float4*)g_agg)[i] = make_float4(0.f, 0.f, 0.f, 0.f);
}
__global__ void zero_misc_kernel(int S)
{
    int i = blockIdx.x * blockDim.x + threadIdx.x;
    if (i < S * D) g_sg[i] = 0.f;
    if (i < S)     g_last[i] = 0;
    if (i < 2)     g_acc[i] = 0.0;
}

// --------------------------------------------- fp32 GEMM 64 (S-row only)
__global__ void __launch_bounds__(256) gemm64(
    int Asel, const float* __restrict__ B,
    int Csel, int nrows, int ldb, int transB,
    const float* __restrict__ bias, int accum)
{
    const float* A = sel_src(Asel);
    float* C = sel_dst(Csel);

    __shared__ float sAt[64][68];
    __shared__ float sB [64][68];
    int tid = threadIdx.x;
    int rowBase = blockIdx.x * 64;

    for (int i = tid; i < 64 * 64; i += 256) {
        int r = i >> 6, k = i & 63;
        int gr = rowBase + r;
        sAt[k][r] = (gr < nrows) ? A[gr * 64 + k] : 0.f;
    }
    if (!transB) {
        for (int i = tid; i < 64 * 64; i += 256) {
            int k = i >> 6, j = i & 63;
            sB[k][j] = B[k * ldb + j];
        }
    } else {
        for (int i = tid; i < 64 * 64; i += 256) {
            int j = i >> 6, k = i & 63;
            sB[k][j] = B[j * ldb + k];
        }
    }
    __syncthreads();

    int r0 = (tid >> 4) * 4, c0 = (tid & 15) * 4;
    float acc[4][4] = {};
#pragma unroll
    for (int k = 0; k < 64; k++) {
        float4 a = *(const float4*)&sAt[k][r0];
        float4 b = *(const float4*)&sB[k][c0];
        float av[4] = {a.x, a.y, a.z, a.w};
        float bv[4] = {b.x, b.y, b.z, b.w};
#pragma unroll
        for (int i = 0; i < 4; i++)
#pragma unroll
            for (int j = 0; j < 4; j++)
                acc[i][j] = fmaf(av[i], bv[j], acc[i][j]);
    }

    float4 bb = make_float4(0.f, 0.f, 0.f, 0.f);
    if (bias) { bb.x = bias[c0]; bb.y = bias[c0 + 1]; bb.z = bias[c0 + 2]; bb.w = bias[c0 + 3]; }
#pragma unroll
    for (int i = 0; i < 4; i++) {
        int gr = rowBase + r0 + i;
        if (gr < nrows) {
            float* cp = C + gr * 64 + c0;
            float4 o;
            o.x = acc[i][0] + bb.x; o.y = acc[i][1] + bb.y;
            o.z = acc[i][2] + bb.z; o.w = acc[i][3] + bb.w;
            if (accum) {
                float4 p = *(const float4*)cp;
                o.x += p.x; o.y += p.y; o.z += p.z; o.w += p.w;
            }
            *(float4*)cp = o;
        }
    }
}

// ------------------------------------------------------------- scatter
__global__ void scatter_kernel(const int* __restrict__ src,
                               const int* __restrict__ dst, int E)
{
    int idx = blockIdx.x * blockDim.x + threadIdx.x;
    int e = idx >> 4;
    if (e >= E) return;
    int c = (idx & 15) << 2;
    int s = __ldg(&src[e]);
    int d = __ldg(&dst[e]);
    float4 v = *(const float4*)&g_m[s * 64 + c];
    float* p = &g_agg[d * 64 + c];
    atomicAdd(p + 0, v.x); atomicAdd(p + 1, v.y);
    atomicAdd(p + 2, v.z); atomicAdd(p + 3, v.w);
}

// ---------------------------------------- tf32 mma: m = h @ ggc[layer]
// 128-row tile, 256 threads (8 warps, warp = 16 rows x 64 cols), K=64.
#define MP 68
#define MSG_SMEM ((128 * MP + 64 * MP) * 4)
__global__ void __launch_bounds__(256) msg_mma(int layer, int nrows)
{
    extern __shared__ uint32_t sm2[];
    uint32_t* sA = sm2;              // [128][MP]
    uint32_t* sB = sm2 + 128 * MP;   // [64][MP]

    int tid = threadIdx.x;
    int lane = tid & 31;
    int warp = tid >> 5;
    int rowBase = blockIdx.x * 128;

    // A fill (tf32) — float4 vectorized
    for (int i = tid; i < 128 * 16; i += 256) {
        int r = i >> 4, q = i & 15;
        int gr = rowBase + r;
        float4 v = make_float4(0.f, 0.f, 0.f, 0.f);
        if (gr < nrows) v = *(const float4*)&g_h[gr * 64 + 4 * q];
        uint4 o = make_uint4(f2tf32(v.x), f2tf32(v.y), f2tf32(v.z), f2tf32(v.w));
        *(uint4*)&sA[r * MP + 4 * q] = o;
    }
    // B fill — straight uint4 copy of prepacked tf32
    const uint32_t* Bsrc = g_msgB + layer * 4096;
    for (int i = tid; i < 64 * 16; i += 256) {
        int c = i >> 4, q = i & 15;
        *(uint4*)&sB[c * MP + 4 * q] = *(const uint4*)&Bsrc[c * 64 + 4 * q];
    }
    __syncthreads();

    int rowW = warp * 16;
    int lr = lane >> 2, lk = lane & 3;
    float acc[8][4];
#pragma unroll
    for (int nt = 0; nt < 8; nt++)
#pragma unroll
        for (int q = 0; q < 4; q++) acc[nt][q] = 0.f;

#pragma unroll
    for (int k0 = 0; k0 < 64; k0 += 8) {
        uint32_t a[4];
        a[0] = sA[(rowW + lr) * MP + k0 + lk];
        a[1] = sA[(rowW + lr + 8) * MP + k0 + lk];
        a[2] = sA[(rowW + lr) * MP + k0 + lk + 4];
        a[3] = sA[(rowW + lr + 8) * MP + k0 + lk + 4];
#pragma unroll
        for (int nt = 0; nt < 8; nt++) {
            uint32_t b0 = sB[(nt * 8 + lr) * MP + k0 + lk];
            uint32_t b1 = sB[(nt * 8 + lr) * MP + k0 + lk + 4];
            mma_tf32(acc[nt], a, b0, b1);
        }
    }

    // direct reg -> gmem store
    int gr0 = rowBase + rowW + lr;
    int gr1 = gr0 + 8;
#pragma unroll
    for (int nt = 0; nt < 8; nt++) {
        int cc = nt * 8 + 2 * lk;
        if (gr0 < nrows) *(float2*)&g_m[gr0 * 64 + cc] = make_float2(acc[nt][0], acc[nt][1]);
        if (gr1 < nrows) *(float2*)&g_m[gr1 * 64 + cc] = make_float2(acc[nt][2], acc[nt][3]);
    }
}

// ------------------------- tf32 mma: hW2 + fused attention gate epilogue
__global__ void __launch_bounds__(256) w2gate_mma(
    const int* __restrict__ batch,
    const float* __restrict__ b1, const float* __restrict__ b2,
    const float* __restrict__ qw, const float* __restrict__ qb,
    int nrows)
{
    extern __shared__ uint32_t sm2[];
    uint32_t* sA = sm2;
    uint32_t* sB = sm2 + 128 * MP;

    int tid = threadIdx.x;
    int lane = tid & 31;
    int warp = tid >> 5;
    int rowBase = blockIdx.x * 128;

    for (int i = tid; i < 128 * 16; i += 256) {
        int r = i >> 4, q = i & 15;
        int gr = rowBase + r;
        float4 v = make_float4(0.f, 0.f, 0.f, 0.f);
        if (gr < nrows) v = *(const float4*)&g_h[gr * 64 + 4 * q];
        uint4 o = make_uint4(f2tf32(v.x), f2tf32(v.y), f2tf32(v.z), f2tf32(v.w));
        *(uint4*)&sA[r * MP + 4 * q] = o;
    }
    for (int i = tid; i < 64 * 16; i += 256) {
        int c = i >> 4, q = i & 15;
        *(uint4*)&sB[c * MP + 4 * q] = *(const uint4*)&g_w2B[c * 64 + 4 * q];
    }
    __syncthreads();

    int rowW = warp * 16;
    int lr = lane >> 2, lk = lane & 3;
    float acc[8][4];
#pragma unroll
    for (int nt = 0; nt < 8; nt++)
#pragma unroll
        for (int q = 0; q < 4; q++) acc[nt][q] = 0.f;

#pragma unroll
    for (int k0 = 0; k0 < 64; k0 += 8) {
        uint32_t a[4];
        a[0] = sA[(rowW + lr) * MP + k0 + lk];
        a[1] = sA[(rowW + lr + 8) * MP + k0 + lk];
        a[2] = sA[(rowW + lr) * MP + k0 + lk + 4];
        a[3] = sA[(rowW + lr + 8) * MP + k0 + lk + 4];
#pragma unroll
        for (int nt = 0; nt < 8; nt++) {
            uint32_t b0 = sB[(nt * 8 + lr) * MP + k0 + lk];
            uint32_t b1 = sB[(nt * 8 + lr) * MP + k0 + lk + 4];
            mma_tf32(acc[nt], a, b0, b1);
        }
    }

    // stage C (hW2) into sA region
    __syncthreads();
    float* sC = (float*)sA;   // [128][MP]
#pragma unroll
    for (int nt = 0; nt < 8; nt++) {
        int cc = nt * 8 + 2 * lk;
        *(float2*)&sC[(rowW + lr) * MP + cc]     = make_float2(acc[nt][0], acc[nt][1]);
        *(float2*)&sC[(rowW + lr + 8) * MP + cc] = make_float2(acc[nt][2], acc[nt][3]);
    }
    __syncthreads();

    // gate epilogue: warp per row
    for (int rr = warp; rr < 128; rr += 8) {
        int gr = rowBase + rr;
        if (gr >= nrows) continue;
        int b = __ldg(&batch[gr]);
        int j0 = lane, j1 = lane + 32;
        float x0 = g_vnW1[b * 64 + j0] + sC[rr * MP + j0] + __ldg(&b1[j0]) + __ldg(&b2[j0]);
        float x1 = g_vnW1[b * 64 + j1] + sC[rr * MP + j1] + __ldg(&b1[j1]) + __ldg(&b2[j1]);
        float gv0 = sigmoidf_(x0), gv1 = sigmoidf_(x1);
        float hv0 = g_h[gr * 64 + j0], hv1 = g_h[gr * 64 + j1];
        float alpha = fmaf(gv0, __ldg(&qw[j0]), gv1 * __ldg(&qw[j1]));
#pragma unroll
        for (int o = 16; o; o >>= 1) alpha += __shfl_xor_sync(0xffffffffu, alpha, o);
        alpha += __ldg(&qb[0]);
        atomicAdd(&g_sg[b * 64 + j0], alpha * hv0);
        atomicAdd(&g_sg[b * 64 + j1], alpha * hv1);
    }
}

// ----------------------------------------------- fused GRU via tf32 mma
#define AP 132
#define BP 132
#define CP 260
#define GRUM_SMEM ((128 * AP + 256 * BP) * 4)

__global__ void __launch_bounds__(512, 1) gru_mma(
    const float* __restrict__ b_ih, const float* __restrict__ b_hh,
    int nrows, int do_relu)
{
    extern __shared__ uint32_t sm[];
    uint32_t* sA = sm;              // [128][AP]
    uint32_t* sB = sm + 128 * AP;   // [256][BP]

    int tid = threadIdx.x;
    int lane = tid & 31;
    int warp = tid >> 5;
    int rowBase = blockIdx.x * 128;

    // A fill (tf32) — float4 vectorized: k<64 from agg, else from h
    for (int i = tid; i < 128 * 32; i += 512) {
        int r = i >> 5, q = i & 31;
        int gr = rowBase + r;
        int k = 4 * q;
        float4 v = make_float4(0.f, 0.f, 0.f, 0.f);
        if (gr < nrows)
            v = (k < 64) ? *(const float4*)&g_agg[gr * 64 + k]
                         : *(const float4*)&g_h[gr * 64 + (k - 64)];
        uint4 o = make_uint4(f2tf32(v.x), f2tf32(v.y), f2tf32(v.z), f2tf32(v.w));
        *(uint4*)&sA[r * AP + k] = o;
    }
    // B fill — uint4 copy of prepacked gate-blocked weights
    for (int i = tid; i < 256 * 32; i += 512) {
        int c = i >> 5, q = i & 31;
        *(uint4*)&sB[c * BP + 4 * q] = *(const uint4*)&g_gruB[c * 128 + 4 * q];
    }
    __syncthreads();

    int rowW = (warp >> 2) * 32;
    int colW = (warp & 3) * 64;
    float acc[2][8][4];
#pragma unroll
    for (int mt = 0; mt < 2; mt++)
#pragma unroll
        for (int nt = 0; nt < 8; nt++)
#pragma unroll
            for (int q = 0; q < 4; q++) acc[mt][nt][q] = 0.f;

    int lr = lane >> 2, lk = lane & 3;
#pragma unroll
    for (int k0 = 0; k0 < 128; k0 += 8) {
        uint32_t a[2][4];
#pragma unroll
        for (int mt = 0; mt < 2; mt++) {
            int r = rowW + mt * 16 + lr;
            a[mt][0] = sA[r * AP + k0 + lk];
            a[mt][1] = sA[(r + 8) * AP + k0 + lk];
            a[mt][2] = sA[r * AP + k0 + lk + 4];
            a[mt][3] = sA[(r + 8) * AP + k0 + lk + 4];
        }
#pragma unroll
        for (int nt = 0; nt < 8; nt++) {
            int cc = colW + nt * 8 + lr;
            uint32_t b0 = sB[cc * BP + k0 + lk];
            uint32_t b1 = sB[cc * BP + k0 + lk + 4];
            mma_tf32(acc[0][nt], a[0], b0, b1);
            mma_tf32(acc[1][nt], a[1], b0, b1);
        }
    }

    // stage C into smem (reuse B region)
    __syncthreads();
    float* sC = (float*)sB;
#pragma unroll
    for (int mt = 0; mt < 2; mt++) {
#pragma unroll
        for (int nt = 0; nt < 8; nt++) {
            int r = rowW + mt * 16 + lr;
            int cc = colW + nt * 8 + (lk << 1);
            *(float2*)&sC[r * CP + cc]       = make_float2(acc[mt][nt][0], acc[mt][nt][1]);
            *(float2*)&sC[(r + 8) * CP + cc] = make_float2(acc[mt][nt][2], acc[mt][nt][3]);
        }
    }
    __syncthreads();

    // GRU elementwise epilogue (exact fp32 h_old)
    for (int i = tid; i < 128 * 64; i += 512) {
        int r = i >> 6, j = i & 63;
        int gr = rowBase + r;
        if (gr >= nrows) continue;
        float rzr = sC[r * CP + j]       + __ldg(&b_ih[j])       + __ldg(&b_hh[j]);
        float rzz = sC[r * CP + 64 + j]  + __ldg(&b_ih[64 + j])  + __ldg(&b_hh[64 + j]);
        float i_n = sC[r * CP + 128 + j] + __ldg(&b_ih[128 + j]);
        float h_n = sC[r * CP + 192 + j] + __ldg(&b_hh[128 + j]);
        float rr = sigmoidf_(rzr);
        float zz = sigmoidf_(rzz);
        float nn = tanhf(i_n + rr * h_n);
        float ho = g_h[gr * 64 + j];
        float val = (1.f - zz) * nn + zz * ho;
        if (do_relu) val = fmaxf(val, 0.f);
        g_h[gr * 64 + j] = val;
    }
}

// ----------------------------------------------------- last-node / v_n
__global__ void lastmax_kernel(const int* __restrict__ batch, int N)
{
    int idx = blockIdx.x * blockDim.x + threadIdx.x;
    if (idx >= N) return;
    atomicMax(&g_last[batch[idx]], idx);
}
__global__ void vngather_kernel(int S)
{
    int idx = blockIdx.x * blockDim.x + threadIdx.x;
    if (idx >= S * D) return;
    int s = idx >> 6;
    g_vn[idx] = g_h[g_last[s] * 64 + (idx & 63)];
}

// ------------------------------------------------------------ BPR loss
__global__ void loss_kernel(const float* __restrict__ item_emb,
                            const int* __restrict__ pos, const int* __restrict__ neg,
                            int S)
{
    int gidx = blockIdx.x * blockDim.x + threadIdx.x;
    int s = gidx >> 5;
    if (s >= S) return;
    int lane = gidx & 31;
    int ip = pos[s], in2 = neg[s];
    float pp = 0.f, np = 0.f, rg = 0.f;
#pragma unroll
    for (int t = 0; t < 2; t++) {
        int j = lane + t * 32;
        float sv = g_sh[s * 64 + j];
        float pe = item_emb[ip * 64 + j];
        float ne = item_emb[in2 * 64 + j];
        pp = fmaf(sv, pe, pp);
        np = fmaf(sv, ne, np);
        rg += sv * sv + pe * pe + ne * ne;
    }
#pragma unroll
    for (int o = 16; o; o >>= 1) {
        pp += __shfl_xor_sync(0xffffffffu, pp, o);
        np += __shfl_xor_sync(0xffffffffu, np, o);
        rg += __shfl_xor_sync(0xffffffffu, rg, o);
    }
    if (lane == 0) {
        float x = pp - np;
        float lsm = (x > 0.f) ? log1pf(expf(-x)) : (-x + log1pf(expf(x)));
        atomicAdd(&g_acc[0], (double)lsm);
        atomicAdd(&g_acc[1], (double)rg);
    }
}

__global__ void finalize_kernel(float* out, int out_size)
{
    double loss = g_acc[0];
    double nr = g_acc[1] * 1e-5;
    float t = (float)(loss + nr), l = (float)loss, r = (float)nr;
    if (out_size > 0) out[0] = t;
    if (out_size > 1) out[1] = l;
    if (out_size > 2) out[2] = r;
    if (out_size > 3) out[3] = r;
    if (out_size > 4) out[4] = r;
}

// ---------------------------------------------------------------- host
extern "C" void kernel_launch(void* const* d_in, const int* in_sizes, int n_in,
                              void* d_out, int out_size)
{
    const float* item_emb = (const float*)d_in[0];
    const float* ggc      = (const float*)d_in[1];
    const float* W_ih     = (const float*)d_in[2];
    const float* b_ih     = (const float*)d_in[3];
    const float* W_hh     = (const float*)d_in[4];
    const float* b_hh     = (const float*)d_in[5];
    const float* W1       = (const float*)d_in[6];
    const float* b1       = (const float*)d_in[7];
    const float* W2       = (const float*)d_in[8];
    const float* b2       = (const float*)d_in[9];
    const float* qw       = (const float*)d_in[10];
    const float* qb       = (const float*)d_in[11];
    const float* W3       = (const float*)d_in[12];
    const float* b3       = (const float*)d_in[13];
    const int* node_items = (const int*)d_in[14];
    const int* edge_index = (const int*)d_in[15];
    const int* batch      = (const int*)d_in[16];
    const int* pos        = (const int*)d_in[17];
    const int* neg        = (const int*)d_in[18];

    int N = in_sizes[14];
    int E = in_sizes[15] / 2;
    int S = in_sizes[17];
    float* out = (float*)d_out;

    cudaFuncSetAttribute(gru_mma,    cudaFuncAttributeMaxDynamicSharedMemorySize, GRUM_SMEM);
    cudaFuncSetAttribute(msg_mma,    cudaFuncAttributeMaxDynamicSharedMemorySize, MSG_SMEM);
    cudaFuncSetAttribute(w2gate_mma, cudaFuncAttributeMaxDynamicSharedMemorySize, MSG_SMEM);

    const int* src = edge_index;
    const int* dst = edge_index + E;
    int nTiles = (N + 127) / 128;

    prepack_kernel<<<(256 * 128 + 2 * 4096 + 4096 + 255) / 256, 256>>>(W_ih, W_hh, ggc, W2);
    zero_misc_kernel<<<(S * D + 255) / 256, 256>>>(S);
    gather_kernel<<<(N * D + 255) / 256, 256>>>(item_emb, node_items, N);

    for (int layer = 0; layer < 2; layer++) {
        msg_mma<<<nTiles, 256, MSG_SMEM>>>(layer, N);
        zero_agg_kernel<<<(N * D / 4 + 255) / 256, 256>>>(N * D / 4);
        scatter_kernel<<<(E * 16 + 255) / 256, 256>>>(src, dst, E);
        gru_mma<<<nTiles, 512, GRUM_SMEM>>>(b_ih, b_hh, N, layer == 1);
    }

    lastmax_kernel<<<(N + 255) / 256, 256>>>(batch, N);
    vngather_kernel<<<(S * D + 255) / 256, 256>>>(S);

    // vnW1 = v_n @ W1^T  (fp32; S rows only)
    gemm64<<<(S + 63) / 64, 256>>>(1, W1, 1, S, 64, 1, nullptr, 0);
    // hW2 + gate fused (tf32)
    w2gate_mma<<<nTiles, 256, MSG_SMEM>>>(batch, b1, b2, qw, qb, N);

    // s_h = [v_n | s_g] @ W3^T + b3
    gemm64<<<(S + 63) / 64, 256>>>(1, W3,      2, S, 128, 1, nullptr, 0);
    gemm64<<<(S + 63) / 64, 256>>>(2, W3 + 64, 2, S, 128, 1, b3, 1);

    loss_kernel<<<(S * 32 + 255) / 256, 256>>>(item_emb, pos, neg, S);
    finalize_kernel<<<1, 1>>>(out, out_size);
}

// round 5
// speedup vs baseline: 2.4902x; 1.3249x over previous
#include <cuda_runtime.h>
#include <math.h>
#include <stdint.h>

#define D 64
#define N_MAX 327680
#define S_MAX 16384

// ---- scratch (static device globals) ----
__device__ float g_h   [N_MAX * D];
__device__ float g_m   [N_MAX * D];
__device__ float g_vn  [S_MAX * D];
__device__ float g_vnW1[S_MAX * D];
__device__ float g_sg  [S_MAX * D];
__device__ float g_sh  [S_MAX * D];
__device__ int   g_last[S_MAX];
__device__ int   g_inedge[N_MAX];     // predecessor node or -1 (indeg<=1 graph)
__device__ double g_acc[2];
// prepacked tf32 weights ([col][k] layouts matching smem B tiles)
__device__ uint32_t g_gruB[256 * 128];
__device__ uint32_t g_msgB[2 * 64 * 64];
__device__ uint32_t g_w2B [64 * 64];

__device__ __forceinline__ float sigmoidf_(float x) { return 1.f / (1.f + expf(-x)); }

__device__ __forceinline__ uint32_t f2tf32(float v) {
    uint32_t o;
    asm("cvt.rna.tf32.f32 %0, %1;" : "=r"(o) : "f"(v));
    return o;
}

__device__ __forceinline__ uint32_t smem_u32(const void* p) {
    return (uint32_t)__cvta_generic_to_shared(p);
}
__device__ __forceinline__ void cp16(uint32_t dst, const void* src) {
    asm volatile("cp.async.cg.shared.global [%0], [%1], 16;" :: "r"(dst), "l"(src));
}
__device__ __forceinline__ void cp16z(uint32_t dst, const void* src, int sz) {
    asm volatile("cp.async.cg.shared.global [%0], [%1], 16, %2;" :: "r"(dst), "l"(src), "r"(sz));
}
__device__ __forceinline__ void cp_commit_wait() {
    asm volatile("cp.async.commit_group;");
    asm volatile("cp.async.wait_group 0;");
}

__device__ __forceinline__ void mma_tf32(float d[4], const uint32_t a[4],
                                         uint32_t b0, uint32_t b1)
{
    asm volatile(
        "mma.sync.aligned.m16n8k8.row.col.f32.tf32.tf32.f32 "
        "{%0,%1,%2,%3}, {%4,%5,%6,%7}, {%8,%9}, {%0,%1,%2,%3};"
        : "+f"(d[0]), "+f"(d[1]), "+f"(d[2]), "+f"(d[3])
        : "r"(a[0]), "r"(a[1]), "r"(a[2]), "r"(a[3]), "r"(b0), "r"(b1));
}

// buffer selectors for the small fp32 gemm (device-side)
__device__ __forceinline__ const float* sel_src(int s) {
    switch (s) {
        case 1: return g_vn;
        case 2: return g_sg;
        default: return g_h;
    }
}
__device__ __forceinline__ float* sel_dst(int s) {
    switch (s) {
        case 1: return g_vnW1;
        case 2: return g_sh;
        default: return g_m;
    }
}

// ------------------------------------------------ weight prepack (tf32)
__global__ void prepack_kernel(const float* __restrict__ W_ih,
                               const float* __restrict__ W_hh,
                               const float* __restrict__ ggc,
                               const float* __restrict__ W2)
{
    int idx = blockIdx.x * blockDim.x + threadIdx.x;
    if (idx < 256 * 128) {
        int c = idx >> 7, k = idx & 127;
        int j = c & 63, g = c >> 6;
        float v;
        if (g == 0)      v = (k < 64) ? W_ih[j * 64 + k]         : W_hh[j * 64 + (k - 64)];
        else if (g == 1) v = (k < 64) ? W_ih[(64 + j) * 64 + k]  : W_hh[(64 + j) * 64 + (k - 64)];
        else if (g == 2) v = (k < 64) ? W_ih[(128 + j) * 64 + k] : 0.f;
        else             v = (k < 64) ? 0.f                       : W_hh[(128 + j) * 64 + (k - 64)];
        g_gruB[idx] = f2tf32(v);
    } else if (idx < 256 * 128 + 2 * 4096) {
        int t = idx - 256 * 128;
        int layer = t >> 12, r = t & 4095;
        int j = r >> 6, k = r & 63;
        g_msgB[t] = f2tf32(ggc[layer * 4096 + k * 64 + j]);
    } else if (idx < 256 * 128 + 2 * 4096 + 4096) {
        int t = idx - (256 * 128 + 2 * 4096);
        g_w2B[t] = f2tf32(W2[t]);
    }
}

// ------------------------------------------------------- init helpers
__global__ void zero_misc_kernel(int S, int N)
{
    int i = blockIdx.x * blockDim.x + threadIdx.x;
    if (i < S * D) g_sg[i] = 0.f;
    if (i < S)     g_last[i] = 0;
    if (i < 2)     g_acc[i] = 0.0;
    if (i < N)     g_inedge[i] = -1;
}
__global__ void build_inedge_kernel(const int* __restrict__ src,
                                    const int* __restrict__ dst, int E)
{
    int e = blockIdx.x * blockDim.x + threadIdx.x;
    if (e < E) g_inedge[dst[e]] = src[e];
}

// --------------------------------------------- fp32 GEMM 64 (S-row only)
__global__ void __launch_bounds__(256) gemm64(
    int Asel, const float* __restrict__ B,
    int Csel, int nrows, int ldb, int transB,
    const float* __restrict__ bias, int accum)
{
    const float* A = sel_src(Asel);
    float* C = sel_dst(Csel);

    __shared__ float sAt[64][68];
    __shared__ float sB [64][68];
    int tid = threadIdx.x;
    int rowBase = blockIdx.x * 64;

    for (int i = tid; i < 64 * 64; i += 256) {
        int r = i >> 6, k = i & 63;
        int gr = rowBase + r;
        sAt[k][r] = (gr < nrows) ? A[gr * 64 + k] : 0.f;
    }
    if (!transB) {
        for (int i = tid; i < 64 * 64; i += 256) {
            int k = i >> 6, j = i & 63;
            sB[k][j] = B[k * ldb + j];
        }
    } else {
        for (int i = tid; i < 64 * 64; i += 256) {
            int j = i >> 6, k = i & 63;
            sB[k][j] = B[j * ldb + k];
        }
    }
    __syncthreads();

    int r0 = (tid >> 4) * 4, c0 = (tid & 15) * 4;
    float acc[4][4] = {};
#pragma unroll
    for (int k = 0; k < 64; k++) {
        float4 a = *(const float4*)&sAt[k][r0];
        float4 b = *(const float4*)&sB[k][c0];
        float av[4] = {a.x, a.y, a.z, a.w};
        float bv[4] = {b.x, b.y, b.z, b.w};
#pragma unroll
        for (int i = 0; i < 4; i++)
#pragma unroll
            for (int j = 0; j < 4; j++)
                acc[i][j] = fmaf(av[i], bv[j], acc[i][j]);
    }

    float4 bb = make_float4(0.f, 0.f, 0.f, 0.f);
    if (bias) { bb.x = bias[c0]; bb.y = bias[c0 + 1]; bb.z = bias[c0 + 2]; bb.w = bias[c0 + 3]; }
#pragma unroll
    for (int i = 0; i < 4; i++) {
        int gr = rowBase + r0 + i;
        if (gr < nrows) {
            float* cp = C + gr * 64 + c0;
            float4 o;
            o.x = acc[i][0] + bb.x; o.y = acc[i][1] + bb.y;
            o.z = acc[i][2] + bb.z; o.w = acc[i][3] + bb.w;
            if (accum) {
                float4 p = *(const float4*)cp;
                o.x += p.x; o.y += p.y; o.z += p.z; o.w += p.w;
            }
            *(float4*)cp = o;
        }
    }
}

// ---------------------------------------- tf32 mma: m = h @ ggc[layer]
// layer 0 additionally performs the embedding lookup and writes g_h.
#define MP 68
#define MSG_SMEM ((128 * MP + 64 * MP) * 4)
__global__ void __launch_bounds__(256) msg_mma(
    int layer, int nrows,
    const float* __restrict__ item_emb, const int* __restrict__ items)
{
    extern __shared__ uint32_t sm2[];
    uint32_t* sA = sm2;              // [128][MP]
    uint32_t* sB = sm2 + 128 * MP;   // [64][MP]
    uint32_t sA_u = smem_u32(sA);
    uint32_t sB_u = smem_u32(sB);

    int tid = threadIdx.x;
    int lane = tid & 31;
    int warp = tid >> 5;
    int rowBase = blockIdx.x * 128;

    if (layer == 0) {
        // embedding lookup: fill smem (raw fp32 bits) AND write g_h
        for (int i = tid; i < 128 * 16; i += 256) {
            int r = i >> 4, q = i & 15;
            int gr = rowBase + r;
            float4 v = make_float4(0.f, 0.f, 0.f, 0.f);
            if (gr < nrows) {
                int it = items[gr] - 1;
                v = *(const float4*)&item_emb[it * 64 + 4 * q];
                *(float4*)&g_h[gr * 64 + 4 * q] = v;
            }
            *(float4*)&sA[r * MP + 4 * q] = v;
        }
        for (int i = tid; i < 64 * 16; i += 256) {
            int c = i >> 4, q = i & 15;
            cp16(sB_u + (c * MP + 4 * q) * 4, &g_msgB[c * 64 + 4 * q]);
        }
    } else {
        const uint32_t* Bsrc = g_msgB + layer * 4096;
        for (int i = tid; i < 128 * 16; i += 256) {
            int r = i >> 4, q = i & 15;
            int gr = rowBase + r;
            cp16z(sA_u + (r * MP + 4 * q) * 4, &g_h[gr * 64 + 4 * q],
                  (gr < nrows) ? 16 : 0);
        }
        for (int i = tid; i < 64 * 16; i += 256) {
            int c = i >> 4, q = i & 15;
            cp16(sB_u + (c * MP + 4 * q) * 4, &Bsrc[c * 64 + 4 * q]);
        }
    }
    cp_commit_wait();
    __syncthreads();

    int rowW = warp * 16;
    int lr = lane >> 2, lk = lane & 3;
    float acc[8][4];
#pragma unroll
    for (int nt = 0; nt < 8; nt++)
#pragma unroll
        for (int q = 0; q < 4; q++) acc[nt][q] = 0.f;

#pragma unroll
    for (int k0 = 0; k0 < 64; k0 += 8) {
        uint32_t a[4];
        a[0] = sA[(rowW + lr) * MP + k0 + lk];
        a[1] = sA[(rowW + lr + 8) * MP + k0 + lk];
        a[2] = sA[(rowW + lr) * MP + k0 + lk + 4];
        a[3] = sA[(rowW + lr + 8) * MP + k0 + lk + 4];
#pragma unroll
        for (int nt = 0; nt < 8; nt++) {
            uint32_t b0 = sB[(nt * 8 + lr) * MP + k0 + lk];
            uint32_t b1 = sB[(nt * 8 + lr) * MP + k0 + lk + 4];
            mma_tf32(acc[nt], a, b0, b1);
        }
    }

    int gr0 = rowBase + rowW + lr;
    int gr1 = gr0 + 8;
#pragma unroll
    for (int nt = 0; nt < 8; nt++) {
        int cc = nt * 8 + 2 * lk;
        if (gr0 < nrows) *(float2*)&g_m[gr0 * 64 + cc] = make_float2(acc[nt][0], acc[nt][1]);
        if (gr1 < nrows) *(float2*)&g_m[gr1 * 64 + cc] = make_float2(acc[nt][2], acc[nt][3]);
    }
}

// ------------------------- tf32 mma: hW2 + fused attention gate epilogue
__global__ void __launch_bounds__(256) w2gate_mma(
    const int* __restrict__ batch,
    const float* __restrict__ b1, const float* __restrict__ b2,
    const float* __restrict__ qw, const float* __restrict__ qb,
    int nrows)
{
    extern __shared__ uint32_t sm2[];
    uint32_t* sA = sm2;
    uint32_t* sB = sm2 + 128 * MP;
    uint32_t sA_u = smem_u32(sA);
    uint32_t sB_u = smem_u32(sB);

    int tid = threadIdx.x;
    int lane = tid & 31;
    int warp = tid >> 5;
    int rowBase = blockIdx.x * 128;

    for (int i = tid; i < 128 * 16; i += 256) {
        int r = i >> 4, q = i & 15;
        int gr = rowBase + r;
        cp16z(sA_u + (r * MP + 4 * q) * 4, &g_h[gr * 64 + 4 * q],
              (gr < nrows) ? 16 : 0);
    }
    for (int i = tid; i < 64 * 16; i += 256) {
        int c = i >> 4, q = i & 15;
        cp16(sB_u + (c * MP + 4 * q) * 4, &g_w2B[c * 64 + 4 * q]);
    }
    cp_commit_wait();
    __syncthreads();

    int rowW = warp * 16;
    int lr = lane >> 2, lk = lane & 3;
    float acc[8][4];
#pragma unroll
    for (int nt = 0; nt < 8; nt++)
#pragma unroll
        for (int q = 0; q < 4; q++) acc[nt][q] = 0.f;

#pragma unroll
    for (int k0 = 0; k0 < 64; k0 += 8) {
        uint32_t a[4];
        a[0] = sA[(rowW + lr) * MP + k0 + lk];
        a[1] = sA[(rowW + lr + 8) * MP + k0 + lk];
        a[2] = sA[(rowW + lr) * MP + k0 + lk + 4];
        a[3] = sA[(rowW + lr + 8) * MP + k0 + lk + 4];
#pragma unroll
        for (int nt = 0; nt < 8; nt++) {
            uint32_t b0 = sB[(nt * 8 + lr) * MP + k0 + lk];
            uint32_t b1 = sB[(nt * 8 + lr) * MP + k0 + lk + 4];
            mma_tf32(acc[nt], a, b0, b1);
        }
    }

    __syncthreads();
    float* sC = (float*)sA;   // [128][MP]
#pragma unroll
    for (int nt = 0; nt < 8; nt++) {
        int cc = nt * 8 + 2 * lk;
        *(float2*)&sC[(rowW + lr) * MP + cc]     = make_float2(acc[nt][0], acc[nt][1]);
        *(float2*)&sC[(rowW + lr + 8) * MP + cc] = make_float2(acc[nt][2], acc[nt][3]);
    }
    __syncthreads();

    for (int rr = warp; rr < 128; rr += 8) {
        int gr = rowBase + rr;
        if (gr >= nrows) continue;
        int b = __ldg(&batch[gr]);
        int j0 = lane, j1 = lane + 32;
        float x0 = g_vnW1[b * 64 + j0] + sC[rr * MP + j0] + __ldg(&b1[j0]) + __ldg(&b2[j0]);
        float x1 = g_vnW1[b * 64 + j1] + sC[rr * MP + j1] + __ldg(&b1[j1]) + __ldg(&b2[j1]);
        float gv0 = sigmoidf_(x0), gv1 = sigmoidf_(x1);
        float hv0 = g_h[gr * 64 + j0], hv1 = g_h[gr * 64 + j1];
        float alpha = fmaf(gv0, __ldg(&qw[j0]), gv1 * __ldg(&qw[j1]));
#pragma unroll
        for (int o = 16; o; o >>= 1) alpha += __shfl_xor_sync(0xffffffffu, alpha, o);
        alpha += __ldg(&qb[0]);
        atomicAdd(&g_sg[b * 64 + j0], alpha * hv0);
        atomicAdd(&g_sg[b * 64 + j1], alpha * hv1);
    }
}

// ----------------------------------------------- fused GRU via tf32 mma
// agg[n] = m[inedge[n]] (indeg<=1 graph) gathered straight into smem A.
#define AP 132
#define BP 132
#define CP 260
#define GRUM_SMEM ((128 * AP + 256 * BP) * 4)

__global__ void __launch_bounds__(512, 1) gru_mma(
    const float* __restrict__ b_ih, const float* __restrict__ b_hh,
    int nrows, int do_relu)
{
    extern __shared__ uint32_t sm[];
    uint32_t* sA = sm;              // [128][AP]
    uint32_t* sB = sm + 128 * AP;   // [256][BP]
    uint32_t sA_u = smem_u32(sA);
    uint32_t sB_u = smem_u32(sB);

    int tid = threadIdx.x;
    int lane = tid & 31;
    int warp = tid >> 5;
    int rowBase = blockIdx.x * 128;

    // A fill: k<64 <- m[inedge[gr]] (zero-fill if none), k>=64 <- h[gr]
    for (int i = tid; i < 128 * 32; i += 512) {
        int r = i >> 5, q = i & 31;
        int gr = rowBase + r;
        int k = 4 * q;
        uint32_t dst = sA_u + (r * AP + k) * 4;
        if (k < 64) {
            int p = (gr < nrows) ? g_inedge[gr] : -1;
            const float* srcp = (p >= 0) ? &g_m[p * 64 + k] : g_m;
            cp16z(dst, srcp, (p >= 0) ? 16 : 0);
        } else {
            cp16z(dst, &g_h[gr * 64 + (k - 64)], (gr < nrows) ? 16 : 0);
        }
    }
    // B fill — prepacked gate-blocked weights
    for (int i = tid; i < 256 * 32; i += 512) {
        int c = i >> 5, q = i & 31;
        cp16(sB_u + (c * BP + 4 * q) * 4, &g_gruB[c * 128 + 4 * q]);
    }
    cp_commit_wait();
    __syncthreads();

    int rowW = (warp >> 2) * 32;
    int colW = (warp & 3) * 64;
    float acc[2][8][4];
#pragma unroll
    for (int mt = 0; mt < 2; mt++)
#pragma unroll
        for (int nt = 0; nt < 8; nt++)
#pragma unroll
            for (int q = 0; q < 4; q++) acc[mt][nt][q] = 0.f;

    int lr = lane >> 2, lk = lane & 3;
#pragma unroll
    for (int k0 = 0; k0 < 128; k0 += 8) {
        uint32_t a[2][4];
#pragma unroll
        for (int mt = 0; mt < 2; mt++) {
            int r = rowW + mt * 16 + lr;
            a[mt][0] = sA[r * AP + k0 + lk];
            a[mt][1] = sA[(r + 8) * AP + k0 + lk];
            a[mt][2] = sA[r * AP + k0 + lk + 4];
            a[mt][3] = sA[(r + 8) * AP + k0 + lk + 4];
        }
#pragma unroll
        for (int nt = 0; nt < 8; nt++) {
            int cc = colW + nt * 8 + lr;
            uint32_t b0 = sB[cc * BP + k0 + lk];
            uint32_t b1 = sB[cc * BP + k0 + lk + 4];
            mma_tf32(acc[0][nt], a[0], b0, b1);
            mma_tf32(acc[1][nt], a[1], b0, b1);
        }
    }

    __syncthreads();
    float* sC = (float*)sB;
#pragma unroll
    for (int mt = 0; mt < 2; mt++) {
#pragma unroll
        for (int nt = 0; nt < 8; nt++) {
            int r = rowW + mt * 16 + lr;
            int cc = colW + nt * 8 + (lk << 1);
            *(float2*)&sC[r * CP + cc]       = make_float2(acc[mt][nt][0], acc[mt][nt][1]);
            *(float2*)&sC[(r + 8) * CP + cc] = make_float2(acc[mt][nt][2], acc[mt][nt][3]);
        }
    }
    __syncthreads();

    for (int i = tid; i < 128 * 64; i += 512) {
        int r = i >> 6, j = i & 63;
        int gr = rowBase + r;
        if (gr >= nrows) continue;
        float rzr = sC[r * CP + j]       + __ldg(&b_ih[j])       + __ldg(&b_hh[j]);
        float rzz = sC[r * CP + 64 + j]  + __ldg(&b_ih[64 + j])  + __ldg(&b_hh[64 + j]);
        float i_n = sC[r * CP + 128 + j] + __ldg(&b_ih[128 + j]);
        float h_n = sC[r * CP + 192 + j] + __ldg(&b_hh[128 + j]);
        float rr = sigmoidf_(rzr);
        float zz = sigmoidf_(rzz);
        float nn = tanhf(i_n + rr * h_n);
        float ho = g_h[gr * 64 + j];
        float val = (1.f - zz) * nn + zz * ho;
        if (do_relu) val = fmaxf(val, 0.f);
        g_h[gr * 64 + j] = val;
    }
}

// ----------------------------------------------------- last-node / v_n
__global__ void lastmax_kernel(const int* __restrict__ batch, int N)
{
    int idx = blockIdx.x * blockDim.x + threadIdx.x;
    if (idx >= N) return;
    atomicMax(&g_last[batch[idx]], idx);
}
__global__ void vngather_kernel(int S)
{
    int idx = blockIdx.x * blockDim.x + threadIdx.x;
    if (idx >= S * D) return;
    int s = idx >> 6;
    g_vn[idx] = g_h[g_last[s] * 64 + (idx & 63)];
}

// ------------------------------------------------------------ BPR loss
__global__ void loss_kernel(const float* __restrict__ item_emb,
                            const int* __restrict__ pos, const int* __restrict__ neg,
                            int S)
{
    int gidx = blockIdx.x * blockDim.x + threadIdx.x;
    int s = gidx >> 5;
    if (s >= S) return;
    int lane = gidx & 31;
    int ip = pos[s], in2 = neg[s];
    float pp = 0.f, np = 0.f, rg = 0.f;
#pragma unroll
    for (int t = 0; t < 2; t++) {
        int j = lane + t * 32;
        float sv = g_sh[s * 64 + j];
        float pe = item_emb[ip * 64 + j];
        float ne = item_emb[in2 * 64 + j];
        pp = fmaf(sv, pe, pp);
        np = fmaf(sv, ne, np);
        rg += sv * sv + pe * pe + ne * ne;
    }
#pragma unroll
    for (int o = 16; o; o >>= 1) {
        pp += __shfl_xor_sync(0xffffffffu, pp, o);
        np += __shfl_xor_sync(0xffffffffu, np, o);
        rg += __shfl_xor_sync(0xffffffffu, rg, o);
    }
    if (lane == 0) {
        float x = pp - np;
        float lsm = (x > 0.f) ? log1pf(expf(-x)) : (-x + log1pf(expf(x)));
        atomicAdd(&g_acc[0], (double)lsm);
        atomicAdd(&g_acc[1], (double)rg);
    }
}

__global__ void finalize_kernel(float* out, int out_size)
{
    double loss = g_acc[0];
    double nr = g_acc[1] * 1e-5;
    float t = (float)(loss + nr), l = (float)loss, r = (float)nr;
    if (out_size > 0) out[0] = t;
    if (out_size > 1) out[1] = l;
    if (out_size > 2) out[2] = r;
    if (out_size > 3) out[3] = r;
    if (out_size > 4) out[4] = r;
}

// ---------------------------------------------------------------- host
extern "C" void kernel_launch(void* const* d_in, const int* in_sizes, int n_in,
                              void* d_out, int out_size)
{
    const float* item_emb = (const float*)d_in[0];
    const float* ggc      = (const float*)d_in[1];
    const float* W_ih     = (const float*)d_in[2];
    const float* b_ih     = (const float*)d_in[3];
    const float* W_hh     = (const float*)d_in[4];
    const float* b_hh     = (const float*)d_in[5];
    const float* W1       = (const float*)d_in[6];
    const float* b1       = (const float*)d_in[7];
    const float* W2       = (const float*)d_in[8];
    const float* b2       = (const float*)d_in[9];
    const float* qw       = (const float*)d_in[10];
    const float* qb       = (const float*)d_in[11];
    const float* W3       = (const float*)d_in[12];
    const float* b3       = (const float*)d_in[13];
    const int* node_items = (const int*)d_in[14];
    const int* edge_index = (const int*)d_in[15];
    const int* batch      = (const int*)d_in[16];
    const int* pos        = (const int*)d_in[17];
    const int* neg        = (const int*)d_in[18];

    int N = in_sizes[14];
    int E = in_sizes[15] / 2;
    int S = in_sizes[17];
    float* out = (float*)d_out;

    cudaFuncSetAttribute(gru_mma,    cudaFuncAttributeMaxDynamicSharedMemorySize, GRUM_SMEM);
    cudaFuncSetAttribute(msg_mma,    cudaFuncAttributeMaxDynamicSharedMemorySize, MSG_SMEM);
    cudaFuncSetAttribute(w2gate_mma, cudaFuncAttributeMaxDynamicSharedMemorySize, MSG_SMEM);

    const int* src = edge_index;
    const int* dst = edge_index + E;
    int nTiles = (N + 127) / 128;
    int initCnt = (N > S * D) ? N : S * D;

    prepack_kernel<<<(256 * 128 + 2 * 4096 + 4096 + 255) / 256, 256>>>(W_ih, W_hh, ggc, W2);
    zero_misc_kernel<<<(initCnt + 255) / 256, 256>>>(S, N);
    build_inedge_kernel<<<(E + 255) / 256, 256>>>(src, dst, E);

    for (int layer = 0; layer < 2; layer++) {
        msg_mma<<<nTiles, 256, MSG_SMEM>>>(layer, N, item_emb, node_items);
        gru_mma<<<nTiles, 512, GRUM_SMEM>>>(b_ih, b_hh, N, layer == 1);
    }

    lastmax_kernel<<<(N + 255) / 256, 256>>>(batch, N);
    vngather_kernel<<<(S * D + 255) / 256, 256>>>(S);

    gemm64<<<(S + 63) / 64, 256>>>(1, W1, 1, S, 64, 1, nullptr, 0);
    w2gate_mma<<<nTiles, 256, MSG_SMEM>>>(batch, b1, b2, qw, qb, N);

    gemm64<<<(S + 63) / 64, 256>>>(1, W3,      2, S, 128, 1, nullptr, 0);
    gemm64<<<(S + 63) / 64, 256>>>(2, W3 + 64, 2, S, 128, 1, b3, 1);

    loss_kernel<<<(S * 32 + 255) / 256, 256>>>(item_emb, pos, neg, S);
    finalize_kernel<<<1, 1>>>(out, out_size);
}

// round 6
// speedup vs baseline: 3.7244x; 1.4956x over previous
#include <cuda_runtime.h>
#include <cuda_bf16.h>
#include <math.h>
#include <stdint.h>

#define D 64
#define N_MAX 327680
#define S_MAX 16384

// ---- scratch (static device globals) ----
__device__ float g_hA  [N_MAX * D];   // h double-buffer A (gather -> L0 in -> L1 out = final)
__device__ float g_hB  [N_MAX * D];   // h double-buffer B (L0 out -> L1 in)
__device__ float g_vn  [S_MAX * D];
__device__ float g_vnW1[S_MAX * D];
__device__ float g_sg  [S_MAX * D];
__device__ float g_sh  [S_MAX * D];
__device__ int   g_last[S_MAX];
__device__ int   g_inedge[N_MAX];     // predecessor node or -1 (indeg<=1 graph)
__device__ double g_acc[2];
// prepacked weights
__device__ __align__(16) uint16_t g_gruBb[256 * 128];  // bf16, col c=4*j+g (gate-interleaved), [c][k]
__device__ __align__(16) uint16_t g_msgGb[2 * 64 * 64];// bf16, [layer][col j][k]
__device__ __align__(16) uint32_t g_w2B [64 * 64];     // tf32, [j][k]

// ---------------------------------------------------------------- helpers
__device__ __forceinline__ float fsigmoid(float x) {
    float e = __expf(-x);
    float r;
    asm("rcp.approx.f32 %0, %1;" : "=f"(r) : "f"(1.f + e));
    return r;
}
__device__ __forceinline__ float ftanh_(float x) {
    float t;
    asm("tanh.approx.f32 %0, %1;" : "=f"(t) : "f"(x));
    return t;
}
__device__ __forceinline__ uint32_t f2tf32(float v) {
    uint32_t o;
    asm("cvt.rna.tf32.f32 %0, %1;" : "=r"(o) : "f"(v));
    return o;
}
__device__ __forceinline__ uint32_t pbf2(float lo, float hi) {
    uint32_t o;
    asm("cvt.rn.bf16x2.f32 %0, %1, %2;" : "=r"(o) : "f"(hi), "f"(lo));
    return o;
}
__device__ __forceinline__ uint32_t smem_u32(const void* p) {
    return (uint32_t)__cvta_generic_to_shared(p);
}
__device__ __forceinline__ void cp16(uint32_t dst, const void* src) {
    asm volatile("cp.async.cg.shared.global [%0], [%1], 16;" :: "r"(dst), "l"(src));
}
__device__ __forceinline__ void mma_bf16(float d[4], const uint32_t a[4],
                                         uint32_t b0, uint32_t b1)
{
    asm volatile(
        "mma.sync.aligned.m16n8k16.row.col.f32.bf16.bf16.f32 "
        "{%0,%1,%2,%3}, {%4,%5,%6,%7}, {%8,%9}, {%0,%1,%2,%3};"
        : "+f"(d[0]), "+f"(d[1]), "+f"(d[2]), "+f"(d[3])
        : "r"(a[0]), "r"(a[1]), "r"(a[2]), "r"(a[3]), "r"(b0), "r"(b1));
}
__device__ __forceinline__ void mma_tf32(float d[4], const uint32_t a[4],
                                         uint32_t b0, uint32_t b1)
{
    asm volatile(
        "mma.sync.aligned.m16n8k8.row.col.f32.tf32.tf32.f32 "
        "{%0,%1,%2,%3}, {%4,%5,%6,%7}, {%8,%9}, {%0,%1,%2,%3};"
        : "+f"(d[0]), "+f"(d[1]), "+f"(d[2]), "+f"(d[3])
        : "r"(a[0]), "r"(a[1]), "r"(a[2]), "r"(a[3]), "r"(b0), "r"(b1));
}

// selectors for small fp32 gemm
__device__ __forceinline__ const float* sel_src(int s) {
    switch (s) { case 1: return g_vn; case 2: return g_sg; default: return g_hA; }
}
__device__ __forceinline__ float* sel_dst(int s) {
    switch (s) { case 1: return g_vnW1; default: return g_sh; }
}

// ------------------------------------------------ weight prepack
__global__ void prepack_kernel(const float* __restrict__ W_ih,
                               const float* __restrict__ W_hh,
                               const float* __restrict__ ggc,
                               const float* __restrict__ W2)
{
    int idx = blockIdx.x * blockDim.x + threadIdx.x;
    if (idx < 256 * 128) {
        int c = idx >> 7, k = idx & 127;
        int j = c >> 2, g = c & 3;     // gate-interleaved columns
        float v;
        if (g == 0)      v = (k < 64) ? W_ih[j * 64 + k]         : W_hh[j * 64 + (k - 64)];
        else if (g == 1) v = (k < 64) ? W_ih[(64 + j) * 64 + k]  : W_hh[(64 + j) * 64 + (k - 64)];
        else if (g == 2) v = (k < 64) ? W_ih[(128 + j) * 64 + k] : 0.f;
        else             v = (k < 64) ? 0.f                       : W_hh[(128 + j) * 64 + (k - 64)];
        g_gruBb[idx] = __bfloat16_as_ushort(__float2bfloat16_rn(v));
    } else if (idx < 256 * 128 + 2 * 4096) {
        int t = idx - 256 * 128;
        int layer = t >> 12, r = t & 4095;
        int j = r >> 6, k = r & 63;
        g_msgGb[t] = __bfloat16_as_ushort(__float2bfloat16_rn(ggc[layer * 4096 + k * 64 + j]));
    } else if (idx < 256 * 128 + 2 * 4096 + 4096) {
        int t = idx - (256 * 128 + 2 * 4096);
        g_w2B[t] = f2tf32(W2[t]);
    }
}

// ------------------------------------------------------- init helpers
__global__ void zero_misc_kernel(int S, int N)
{
    int i = blockIdx.x * blockDim.x + threadIdx.x;
    if (i < S * D) g_sg[i] = 0.f;
    if (i < S)     g_last[i] = 0;
    if (i < 2)     g_acc[i] = 0.0;
    if (i < N)     g_inedge[i] = -1;
}
__global__ void build_inedge_kernel(const int* __restrict__ src,
                                    const int* __restrict__ dst, int E)
{
    int e = blockIdx.x * blockDim.x + threadIdx.x;
    if (e < E) g_inedge[dst[e]] = src[e];
}
__global__ void gather_kernel(const float* __restrict__ item_emb,
                              const int* __restrict__ items, int N)
{
    int idx = blockIdx.x * blockDim.x + threadIdx.x;
    if (idx >= N * 16) return;
    int n = idx >> 4, q = idx & 15;
    int it = items[n] - 1;
    *(float4*)&g_hA[n * 64 + 4 * q] = *(const float4*)&item_emb[it * 64 + 4 * q];
}

// --------------------------------------------- fp32 GEMM 64 (S-row only)
__global__ void __launch_bounds__(256) gemm64(
    int Asel, const float* __restrict__ B,
    int Csel, int nrows, int ldb,
    const float* __restrict__ bias, int accum)
{
    const float* A = sel_src(Asel);
    float* C = sel_dst(Csel);

    __shared__ float sAt[64][68];
    __shared__ float sB [64][68];
    int tid = threadIdx.x;
    int rowBase = blockIdx.x * 64;

    for (int i = tid; i < 64 * 64; i += 256) {
        int r = i >> 6, k = i & 63;
        int gr = rowBase + r;
        sAt[k][r] = (gr < nrows) ? A[gr * 64 + k] : 0.f;
    }
    for (int i = tid; i < 64 * 64; i += 256) {
        int j = i >> 6, k = i & 63;
        sB[k][j] = B[j * ldb + k];   // transB always (W @ x^T form)
    }
    __syncthreads();

    int r0 = (tid >> 4) * 4, c0 = (tid & 15) * 4;
    float acc[4][4] = {};
#pragma unroll
    for (int k = 0; k < 64; k++) {
        float4 a = *(const float4*)&sAt[k][r0];
        float4 b = *(const float4*)&sB[k][c0];
        float av[4] = {a.x, a.y, a.z, a.w};
        float bv[4] = {b.x, b.y, b.z, b.w};
#pragma unroll
        for (int i = 0; i < 4; i++)
#pragma unroll
            for (int j = 0; j < 4; j++)
                acc[i][j] = fmaf(av[i], bv[j], acc[i][j]);
    }

    float4 bb = make_float4(0.f, 0.f, 0.f, 0.f);
    if (bias) { bb.x = bias[c0]; bb.y = bias[c0 + 1]; bb.z = bias[c0 + 2]; bb.w = bias[c0 + 3]; }
#pragma unroll
    for (int i = 0; i < 4; i++) {
        int gr = rowBase + r0 + i;
        if (gr < nrows) {
            float* cp = C + gr * 64 + c0;
            float4 o;
            o.x = acc[i][0] + bb.x; o.y = acc[i][1] + bb.y;
            o.z = acc[i][2] + bb.z; o.w = acc[i][3] + bb.w;
            if (accum) {
                float4 p = *(const float4*)cp;
                o.x += p.x; o.y += p.y; o.z += p.z; o.w += p.w;
            }
            *(float4*)cp = o;
        }
    }
}

// ============================= fused msg + GRU (bf16 mma, per 64-row tile)
// Phase 1: P = h[pred(rows)] @ G[layer]  (K=64)  -> agg half of A
// Phase 2: C = [agg | h] @ Bgru (gate-interleaved cols, K=128, N=256)
// Epilogue: register GRU with shfl gate-exchange; exact fp32 h_old from hin.
#define AKP 136
#define BKP 136
#define HKP 72
#define GRUF_SMEM ((64 * AKP + 256 * BKP) * 2)

__global__ void __launch_bounds__(256, 2) gru_fused(
    int dir, const float* __restrict__ b_ih, const float* __restrict__ b_hh,
    int nrows, int do_relu, int layer)
{
    extern __shared__ uint16_t smh[];
    uint16_t* sA = smh;                 // [64][AKP]  k<64: agg (phase-1 out), k>=64: h
    uint16_t* sB = smh + 64 * AKP;      // [256][BKP] gru weights
    uint16_t* sH = sB;                  // alias: [64][HKP] pred-h tile (phase 1)
    uint16_t* sG = sB + 64 * HKP;       // alias: [64][HKP] msg weights

    const float* hin = dir ? g_hB : g_hA;
    float* hout      = dir ? g_hA : g_hB;

    int tid = threadIdx.x;
    int lane = tid & 31;
    int warp = tid >> 5;
    int lr = lane >> 2, lk = lane & 3;
    int rowBase = blockIdx.x * 64;

    // ---- fills ----
    for (int i = tid; i < 64 * 8; i += 256) {          // h -> sA[k>=64] (bf16 rn)
        int r = i >> 3, seg = (i & 7) * 8;
        int gr = rowBase + r;
        float4 v0 = make_float4(0.f,0.f,0.f,0.f), v1 = v0;
        if (gr < nrows) {
            v0 = *(const float4*)&hin[gr * 64 + seg];
            v1 = *(const float4*)&hin[gr * 64 + seg + 4];
        }
        uint32_t* dp = (uint32_t*)&sA[r * AKP + 64 + seg];
        dp[0] = pbf2(v0.x, v0.y); dp[1] = pbf2(v0.z, v0.w);
        dp[2] = pbf2(v1.x, v1.y); dp[3] = pbf2(v1.z, v1.w);
    }
    for (int i = tid; i < 64 * 8; i += 256) {          // h[pred] -> sH
        int r = i >> 3, seg = (i & 7) * 8;
        int gr = rowBase + r;
        int p = (gr < nrows) ? __ldg(&g_inedge[gr]) : -1;
        float4 v0 = make_float4(0.f,0.f,0.f,0.f), v1 = v0;
        if (p >= 0) {
            v0 = *(const float4*)&hin[p * 64 + seg];
            v1 = *(const float4*)&hin[p * 64 + seg + 4];
        }
        uint32_t* dp = (uint32_t*)&sH[r * HKP + seg];
        dp[0] = pbf2(v0.x, v0.y); dp[1] = pbf2(v0.z, v0.w);
        dp[2] = pbf2(v1.x, v1.y); dp[3] = pbf2(v1.z, v1.w);
    }
    for (int i = tid; i < 64 * 8; i += 256) {          // msg weights -> sG (group)
        int c = i >> 3, q = (i & 7) * 8;
        cp16(smem_u32(&sG[c * HKP + q]), &g_msgGb[layer * 4096 + c * 64 + q]);
    }
    asm volatile("cp.async.commit_group;");
    for (int i = tid; i < 188 * 16; i += 256) {        // gruB tail (c>=68; no sH/sG overlap)
        int c = 68 + (i >> 4), q = (i & 15) * 8;
        cp16(smem_u32(&sB[c * BKP + q]), &g_gruBb[c * 128 + q]);
    }
    asm volatile("cp.async.commit_group;");
    asm volatile("cp.async.wait_group 1;");            // sG ready; tail may float
    __syncthreads();

    // ---- phase 1: P = sH @ sG  (16 rows x 32 cols per warp) ----
    {
        int rowW1 = (warp >> 1) * 16;
        int colW1 = (warp & 1) * 32;
        float p[4][4] = {};
#pragma unroll
        for (int k0 = 0; k0 < 64; k0 += 16) {
            uint32_t a[4];
            a[0] = *(const uint32_t*)&sH[(rowW1 + lr) * HKP + k0 + 2 * lk];
            a[1] = *(const uint32_t*)&sH[(rowW1 + lr + 8) * HKP + k0 + 2 * lk];
            a[2] = *(const uint32_t*)&sH[(rowW1 + lr) * HKP + k0 + 8 + 2 * lk];
            a[3] = *(const uint32_t*)&sH[(rowW1 + lr + 8) * HKP + k0 + 8 + 2 * lk];
#pragma unroll
            for (int nt = 0; nt < 4; nt++) {
                int c = colW1 + nt * 8 + lr;
                uint32_t b0 = *(const uint32_t*)&sG[c * HKP + k0 + 2 * lk];
                uint32_t b1 = *(const uint32_t*)&sG[c * HKP + k0 + 8 + 2 * lk];
                mma_bf16(p[nt], a, b0, b1);
            }
        }
#pragma unroll
        for (int nt = 0; nt < 4; nt++) {
            int c0 = colW1 + nt * 8 + 2 * lk;
            *(uint32_t*)&sA[(rowW1 + lr) * AKP + c0]     = pbf2(p[nt][0], p[nt][1]);
            *(uint32_t*)&sA[(rowW1 + lr + 8) * AKP + c0] = pbf2(p[nt][2], p[nt][3]);
        }
    }
    __syncthreads();                                   // sH/sG reads done
    for (int i = tid; i < 68 * 16; i += 256) {         // gruB head (c<68)
        int c = i >> 4, q = (i & 15) * 8;
        cp16(smem_u32(&sB[c * BKP + q]), &g_gruBb[c * 128 + q]);
    }
    asm volatile("cp.async.commit_group;");
    asm volatile("cp.async.wait_group 0;");
    __syncthreads();

    // ---- phase 2: C = [agg|h] @ Bgru  (warp: 32 rows x 64 cols) ----
    int rowW = (warp >> 2) * 32;
    int colW = (warp & 3) * 64;
    float acc[2][8][4];
#pragma unroll
    for (int mt = 0; mt < 2; mt++)
#pragma unroll
        for (int nt = 0; nt < 8; nt++)
#pragma unroll
            for (int q = 0; q < 4; q++) acc[mt][nt][q] = 0.f;

#pragma unroll
    for (int k0 = 0; k0 < 128; k0 += 16) {
        uint32_t a[2][4];
#pragma unroll
        for (int mt = 0; mt < 2; mt++) {
            int r = rowW + mt * 16 + lr;
            a[mt][0] = *(const uint32_t*)&sA[r * AKP + k0 + 2 * lk];
            a[mt][1] = *(const uint32_t*)&sA[(r + 8) * AKP + k0 + 2 * lk];
            a[mt][2] = *(const uint32_t*)&sA[r * AKP + k0 + 8 + 2 * lk];
            a[mt][3] = *(const uint32_t*)&sA[(r + 8) * AKP + k0 + 8 + 2 * lk];
        }
#pragma unroll
        for (int nt = 0; nt < 8; nt++) {
            int c = colW + nt * 8 + lr;
            uint32_t b0 = *(const uint32_t*)&sB[c * BKP + k0 + 2 * lk];
            uint32_t b1 = *(const uint32_t*)&sB[c * BKP + k0 + 8 + 2 * lk];
            mma_bf16(acc[0][nt], a[0], b0, b1);
            mma_bf16(acc[1][nt], a[1], b0, b1);
        }
    }

    // ---- register GRU epilogue ----
    // col c = colW + 8*nt + 2*lk + {0,1} = 4*j + g;  j = colW/4 + 2*nt + (lk>>1)
    int base_j = colW >> 2;
    int odd = lk & 1;
#pragma unroll
    for (int mt = 0; mt < 2; mt++) {
        int r0g = rowBase + rowW + 16 * mt + lr;
        int r1g = r0g + 8;
#pragma unroll
        for (int nt = 0; nt < 8; nt++) {
            int j = base_j + 2 * nt + ((lk >> 1) & 1);
            float s0 = acc[mt][nt][0], s1 = acc[mt][nt][1];
            float s2 = acc[mt][nt][2], s3 = acc[mt][nt][3];
            float e0 = __shfl_xor_sync(0xffffffffu, s0, 1);
            float e1 = __shfl_xor_sync(0xffffffffu, s1, 1);
            float e2 = __shfl_xor_sync(0xffffffffu, s2, 1);
            float e3 = __shfl_xor_sync(0xffffffffu, s3, 1);
            float xr0 = odd ? e0 : s0, xz0 = odd ? e1 : s1;
            float xi0 = odd ? s0 : e0, xn0 = odd ? s1 : e1;
            float xr1 = odd ? e2 : s2, xz1 = odd ? e3 : s3;
            float xi1 = odd ? s2 : e2, xn1 = odd ? s3 : e3;
            float br = __ldg(&b_ih[j])       + __ldg(&b_hh[j]);
            float bz = __ldg(&b_ih[64 + j])  + __ldg(&b_hh[64 + j]);
            float bi = __ldg(&b_ih[128 + j]);
            float bn = __ldg(&b_hh[128 + j]);
            float ho0 = (r0g < nrows) ? hin[r0g * 64 + j] : 0.f;
            float ho1 = (r1g < nrows) ? hin[r1g * 64 + j] : 0.f;
            float rr0 = fsigmoid(xr0 + br), zz0 = fsigmoid(xz0 + bz);
            float nn0 = ftanh_(fmaf(rr0, xn0 + bn, xi0 + bi));
            float v0 = fmaf(zz0, ho0 - nn0, nn0);
            float rr1 = fsigmoid(xr1 + br), zz1 = fsigmoid(xz1 + bz);
            float nn1 = ftanh_(fmaf(rr1, xn1 + bn, xi1 + bi));
            float v1 = fmaf(zz1, ho1 - nn1, nn1);
            if (do_relu) { v0 = fmaxf(v0, 0.f); v1 = fmaxf(v1, 0.f); }
            float w0 = __shfl_xor_sync(0xffffffffu, v0, 2);  // partner holds j+1
            float w1 = __shfl_xor_sync(0xffffffffu, v1, 2);
            if (lk == 0) {
                if (r0g < nrows) *(float2*)&hout[r0g * 64 + j] = make_float2(v0, w0);
                if (r1g < nrows) *(float2*)&hout[r1g * 64 + j] = make_float2(v1, w1);
            }
        }
    }
}

// ------------------------- tf32 mma: hW2 + fused attention gate epilogue
#define MP 68
#define W2_SMEM ((128 * MP + 64 * MP) * 4)
__global__ void __launch_bounds__(256) w2gate_mma(
    const int* __restrict__ batch,
    const float* __restrict__ b1, const float* __restrict__ b2,
    const float* __restrict__ qw, const float* __restrict__ qb,
    int nrows)
{
    extern __shared__ uint32_t sm2[];
    uint32_t* sA = sm2;
    uint32_t* sB = sm2 + 128 * MP;

    int tid = threadIdx.x;
    int lane = tid & 31;
    int warp = tid >> 5;
    int rowBase = blockIdx.x * 128;

    for (int i = tid; i < 128 * 16; i += 256) {   // rna-rounded A fill
        int r = i >> 4, q = i & 15;
        int gr = rowBase + r;
        float4 v = make_float4(0.f,0.f,0.f,0.f);
        if (gr < nrows) v = *(const float4*)&g_hA[gr * 64 + 4 * q];
        uint4 o = make_uint4(f2tf32(v.x), f2tf32(v.y), f2tf32(v.z), f2tf32(v.w));
        *(uint4*)&sA[r * MP + 4 * q] = o;
    }
    for (int i = tid; i < 64 * 16; i += 256) {
        int c = i >> 4, q = i & 15;
        cp16(smem_u32(&sB[c * MP + 4 * q]), &g_w2B[c * 64 + 4 * q]);
    }
    asm volatile("cp.async.commit_group;");
    asm volatile("cp.async.wait_group 0;");
    __syncthreads();

    int rowW = warp * 16;
    int lr = lane >> 2, lk = lane & 3;
    float acc[8][4];
#pragma unroll
    for (int nt = 0; nt < 8; nt++)
#pragma unroll
        for (int q = 0; q < 4; q++) acc[nt][q] = 0.f;

#pragma unroll
    for (int k0 = 0; k0 < 64; k0 += 8) {
        uint32_t a[4];
        a[0] = sA[(rowW + lr) * MP + k0 + lk];
        a[1] = sA[(rowW + lr + 8) * MP + k0 + lk];
        a[2] = sA[(rowW + lr) * MP + k0 + lk + 4];
        a[3] = sA[(rowW + lr + 8) * MP + k0 + lk + 4];
#pragma unroll
        for (int nt = 0; nt < 8; nt++) {
            uint32_t b0 = sB[(nt * 8 + lr) * MP + k0 + lk];
            uint32_t b1 = sB[(nt * 8 + lr) * MP + k0 + lk + 4];
            mma_tf32(acc[nt], a, b0, b1);
        }
    }

    __syncthreads();
    float* sC = (float*)sA;
#pragma unroll
    for (int nt = 0; nt < 8; nt++) {
        int cc = nt * 8 + 2 * lk;
        *(float2*)&sC[(rowW + lr) * MP + cc]     = make_float2(acc[nt][0], acc[nt][1]);
        *(float2*)&sC[(rowW + lr + 8) * MP + cc] = make_float2(acc[nt][2], acc[nt][3]);
    }
    __syncthreads();

    for (int rr = warp; rr < 128; rr += 8) {
        int gr = rowBase + rr;
        if (gr >= nrows) continue;
        int b = __ldg(&batch[gr]);
        int j0 = lane, j1 = lane + 32;
        float x0 = g_vnW1[b * 64 + j0] + sC[rr * MP + j0] + __ldg(&b1[j0]) + __ldg(&b2[j0]);
        float x1 = g_vnW1[b * 64 + j1] + sC[rr * MP + j1] + __ldg(&b1[j1]) + __ldg(&b2[j1]);
        float gv0 = fsigmoid(x0), gv1 = fsigmoid(x1);
        float hv0 = g_hA[gr * 64 + j0], hv1 = g_hA[gr * 64 + j1];
        float alpha = fmaf(gv0, __ldg(&qw[j0]), gv1 * __ldg(&qw[j1]));
#pragma unroll
        for (int o = 16; o; o >>= 1) alpha += __shfl_xor_sync(0xffffffffu, alpha, o);
        alpha += __ldg(&qb[0]);
        atomicAdd(&g_sg[b * 64 + j0], alpha * hv0);
        atomicAdd(&g_sg[b * 64 + j1], alpha * hv1);
    }
}

// ----------------------------------------------------- last-node / v_n
__global__ void lastmax_kernel(const int* __restrict__ batch, int N)
{
    int idx = blockIdx.x * blockDim.x + threadIdx.x;
    if (idx >= N) return;
    atomicMax(&g_last[batch[idx]], idx);
}
__global__ void vngather_kernel(int S)
{
    int idx = blockIdx.x * blockDim.x + threadIdx.x;
    if (idx >= S * D) return;
    int s = idx >> 6;
    g_vn[idx] = g_hA[g_last[s] * 64 + (idx & 63)];
}

// ------------------------------------------------------------ BPR loss
__global__ void loss_kernel(const float* __restrict__ item_emb,
                            const int* __restrict__ pos, const int* __restrict__ neg,
                            int S)
{
    int gidx = blockIdx.x * blockDim.x + threadIdx.x;
    int s = gidx >> 5;
    if (s >= S) return;
    int lane = gidx & 31;
    int ip = pos[s], in2 = neg[s];
    float pp = 0.f, np = 0.f, rg = 0.f;
#pragma unroll
    for (int t = 0; t < 2; t++) {
        int j = lane + t * 32;
        float sv = g_sh[s * 64 + j];
        float pe = item_emb[ip * 64 + j];
        float ne = item_emb[in2 * 64 + j];
        pp = fmaf(sv, pe, pp);
        np = fmaf(sv, ne, np);
        rg += sv * sv + pe * pe + ne * ne;
    }
#pragma unroll
    for (int o = 16; o; o >>= 1) {
        pp += __shfl_xor_sync(0xffffffffu, pp, o);
        np += __shfl_xor_sync(0xffffffffu, np, o);
        rg += __shfl_xor_sync(0xffffffffu, rg, o);
    }
    if (lane == 0) {
        float x = pp - np;
        float lsm = (x > 0.f) ? log1pf(expf(-x)) : (-x + log1pf(expf(x)));
        atomicAdd(&g_acc[0], (double)lsm);
        atomicAdd(&g_acc[1], (double)rg);
    }
}

__global__ void finalize_kernel(float* out, int out_size)
{
    double loss = g_acc[0];
    double nr = g_acc[1] * 1e-5;
    float t = (float)(loss + nr), l = (float)loss, r = (float)nr;
    if (out_size > 0) out[0] = t;
    if (out_size > 1) out[1] = l;
    if (out_size > 2) out[2] = r;
    if (out_size > 3) out[3] = r;
    if (out_size > 4) out[4] = r;
}

// ---------------------------------------------------------------- host
extern "C" void kernel_launch(void* const* d_in, const int* in_sizes, int n_in,
                              void* d_out, int out_size)
{
    const float* item_emb = (const float*)d_in[0];
    const float* ggc      = (const float*)d_in[1];
    const float* W_ih     = (const float*)d_in[2];
    const float* b_ih     = (const float*)d_in[3];
    const float* W_hh     = (const float*)d_in[4];
    const float* b_hh     = (const float*)d_in[5];
    const float* W1       = (const float*)d_in[6];
    const float* b1       = (const float*)d_in[7];
    const float* W2       = (const float*)d_in[8];
    const float* b2       = (const float*)d_in[9];
    const float* qw       = (const float*)d_in[10];
    const float* qb       = (const float*)d_in[11];
    const float* W3       = (const float*)d_in[12];
    const float* b3       = (const float*)d_in[13];
    const int* node_items = (const int*)d_in[14];
    const int* edge_index = (const int*)d_in[15];
    const int* batch      = (const int*)d_in[16];
    const int* pos        = (const int*)d_in[17];
    const int* neg        = (const int*)d_in[18];

    int N = in_sizes[14];
    int E = in_sizes[15] / 2;
    int S = in_sizes[17];
    float* out = (float*)d_out;

    cudaFuncSetAttribute(gru_fused,  cudaFuncAttributeMaxDynamicSharedMemorySize, GRUF_SMEM);
    cudaFuncSetAttribute(w2gate_mma, cudaFuncAttributeMaxDynamicSharedMemorySize, W2_SMEM);

    const int* src = edge_index;
    const int* dst = edge_index + E;
    int gTiles = (N + 63) / 64;
    int nTiles = (N + 127) / 128;
    int initCnt = (N > S * D) ? N : S * D;

    prepack_kernel<<<(256 * 128 + 3 * 4096 + 255) / 256, 256>>>(W_ih, W_hh, ggc, W2);
    zero_misc_kernel<<<(initCnt + 255) / 256, 256>>>(S, N);
    build_inedge_kernel<<<(E + 255) / 256, 256>>>(src, dst, E);
    gather_kernel<<<(N * 16 + 255) / 256, 256>>>(item_emb, node_items, N);

    // layer 0: g_hA -> g_hB ; layer 1: g_hB -> g_hA (+relu)
    gru_fused<<<gTiles, 256, GRUF_SMEM>>>(0, b_ih, b_hh, N, 0, 0);
    gru_fused<<<gTiles, 256, GRUF_SMEM>>>(1, b_ih, b_hh, N, 1, 1);

    lastmax_kernel<<<(N + 255) / 256, 256>>>(batch, N);
    vngather_kernel<<<(S * D + 255) / 256, 256>>>(S);

    gemm64<<<(S + 63) / 64, 256>>>(1, W1, 1, S, 64, nullptr, 0);          // vnW1
    w2gate_mma<<<nTiles, 256, W2_SMEM>>>(batch, b1, b2, qw, qb, N);

    gemm64<<<(S + 63) / 64, 256>>>(1, W3,      2, S, 128, nullptr, 0);    // v_n part
    gemm64<<<(S + 63) / 64, 256>>>(2, W3 + 64, 2, S, 128, b3, 1);         // s_g part

    loss_kernel<<<(S * 32 + 255) / 256, 256>>>(item_emb, pos, neg, S);
    finalize_kernel<<<1, 1>>>(out, out_size);
}

// round 7
// speedup vs baseline: 3.7696x; 1.0121x over previous
#include <cuda_runtime.h>
#include <cuda_bf16.h>
#include <math.h>
#include <stdint.h>

#define D 64
#define N_MAX 327680
#define S_MAX 16384

// ---- scratch ----
__device__ float g_hA  [N_MAX * D];   // final h (written by layer 1)
__device__ float g_hB  [N_MAX * D];   // layer-0 output
__device__ float g_vnW1[S_MAX * D];
__device__ float g_sg  [S_MAX * D];
__device__ float g_sh  [S_MAX * D];
__device__ int   g_last[S_MAX];
__device__ int   g_inedge[N_MAX];
__device__ double g_acc[2];
__device__ __align__(16) uint16_t g_gruBb[256 * 128];   // bf16 gate-interleaved [c=4j+g][k]
__device__ __align__(16) uint16_t g_msgGb[2 * 64 * 64]; // bf16 [layer][col j][k]
__device__ __align__(16) uint16_t g_w2Bb [64 * 64];     // bf16 [j][k]

// ---------------------------------------------------------------- helpers
__device__ __forceinline__ float fsigmoid(float x) {
    float e = __expf(-x);
    float r;
    asm("rcp.approx.f32 %0, %1;" : "=f"(r) : "f"(1.f + e));
    return r;
}
__device__ __forceinline__ float ftanh_(float x) {
    float t;
    asm("tanh.approx.f32 %0, %1;" : "=f"(t) : "f"(x));
    return t;
}
__device__ __forceinline__ uint32_t pbf2(float lo, float hi) {
    uint32_t o;
    asm("cvt.rn.bf16x2.f32 %0, %1, %2;" : "=r"(o) : "f"(hi), "f"(lo));
    return o;
}
__device__ __forceinline__ uint32_t smem_u32(const void* p) {
    return (uint32_t)__cvta_generic_to_shared(p);
}
__device__ __forceinline__ void cp16(uint32_t dst, const void* src) {
    asm volatile("cp.async.cg.shared.global [%0], [%1], 16;" :: "r"(dst), "l"(src));
}
__device__ __forceinline__ void mma_bf16(float d[4], const uint32_t a[4],
                                         uint32_t b0, uint32_t b1)
{
    asm volatile(
        "mma.sync.aligned.m16n8k16.row.col.f32.bf16.bf16.f32 "
        "{%0,%1,%2,%3}, {%4,%5,%6,%7}, {%8,%9}, {%0,%1,%2,%3};"
        : "+f"(d[0]), "+f"(d[1]), "+f"(d[2]), "+f"(d[3])
        : "r"(a[0]), "r"(a[1]), "r"(a[2]), "r"(a[3]), "r"(b0), "r"(b1));
}

// ------------------------------------------------ weight prepack (bf16)
__global__ void prepack_kernel(const float* __restrict__ W_ih,
                               const float* __restrict__ W_hh,
                               const float* __restrict__ ggc,
                               const float* __restrict__ W2)
{
    int idx = blockIdx.x * blockDim.x + threadIdx.x;
    if (idx < 256 * 128) {
        int c = idx >> 7, k = idx & 127;
        int j = c >> 2, g = c & 3;
        float v;
        if (g == 0)      v = (k < 64) ? W_ih[j * 64 + k]         : W_hh[j * 64 + (k - 64)];
        else if (g == 1) v = (k < 64) ? W_ih[(64 + j) * 64 + k]  : W_hh[(64 + j) * 64 + (k - 64)];
        else if (g == 2) v = (k < 64) ? W_ih[(128 + j) * 64 + k] : 0.f;
        else             v = (k < 64) ? 0.f                       : W_hh[(128 + j) * 64 + (k - 64)];
        g_gruBb[idx] = __bfloat16_as_ushort(__float2bfloat16_rn(v));
    } else if (idx < 256 * 128 + 2 * 4096) {
        int t = idx - 256 * 128;
        int layer = t >> 12, r = t & 4095;
        int j = r >> 6, k = r & 63;
        g_msgGb[t] = __bfloat16_as_ushort(__float2bfloat16_rn(ggc[layer * 4096 + k * 64 + j]));
    } else if (idx < 256 * 128 + 2 * 4096 + 4096) {
        int t = idx - (256 * 128 + 2 * 4096);
        g_w2Bb[t] = __bfloat16_as_ushort(__float2bfloat16_rn(W2[t]));
    }
}

// ------------------------------------------------------- init helpers
__global__ void zero_misc_kernel(int S, int N)
{
    int i = blockIdx.x * blockDim.x + threadIdx.x;
    if (i < S * D) g_sg[i] = 0.f;
    if (i < S)     g_last[i] = 0;
    if (i < 2)     g_acc[i] = 0.0;
    if (i < N)     g_inedge[i] = -1;
}
__global__ void build_inedge_kernel(const int* __restrict__ src,
                                    const int* __restrict__ dst, int E)
{
    int e = blockIdx.x * blockDim.x + threadIdx.x;
    if (e < E) g_inedge[dst[e]] = src[e];
}
__global__ void lastmax_kernel(const int* __restrict__ batch, int N)
{
    int idx = blockIdx.x * blockDim.x + threadIdx.x;
    if (idx >= N) return;
    atomicMax(&g_last[batch[idx]], idx);
}

// ============================= fused msg + GRU (bf16 mma, 128-row tiles)
#define AKP 136
#define BKP 136
#define HKP 72
#define GRUF_SMEM ((128 * AKP + 256 * BKP) * 2)

__global__ void __launch_bounds__(256, 2) gru_fused(
    int dir, const float* __restrict__ b_ih, const float* __restrict__ b_hh,
    int nrows, int do_relu, int layer,
    const float* __restrict__ emb, const int* __restrict__ items)
{
    extern __shared__ uint16_t smh[];
    uint16_t* sA = smh;                 // [128][AKP]  k<64: agg, k>=64: h
    uint16_t* sB = smh + 128 * AKP;     // [256][BKP]
    uint16_t* sH = sB;                  // alias [128][HKP]
    uint16_t* sG = sB + 128 * HKP;      // alias [64][HKP]

    const float* hin = dir ? g_hB : g_hA;
    float* hout      = dir ? g_hA : g_hB;

    int tid = threadIdx.x;
    int lane = tid & 31;
    int warp = tid >> 5;
    int lr = lane >> 2, lk = lane & 3;
    int rowBase = blockIdx.x * 128;

    // ---- fills ----
    for (int i = tid; i < 128 * 8; i += 256) {          // h (or emb) -> sA[k>=64]
        int r = i >> 3, seg = (i & 7) * 8;
        int gr = rowBase + r;
        float4 v0 = make_float4(0.f,0.f,0.f,0.f), v1 = v0;
        if (gr < nrows) {
            const float* sp = (layer == 0) ? emb + (size_t)(__ldg(&items[gr]) - 1) * 64
                                           : hin + (size_t)gr * 64;
            v0 = *(const float4*)&sp[seg];
            v1 = *(const float4*)&sp[seg + 4];
        }
        uint32_t* dp = (uint32_t*)&sA[r * AKP + 64 + seg];
        dp[0] = pbf2(v0.x, v0.y); dp[1] = pbf2(v0.z, v0.w);
        dp[2] = pbf2(v1.x, v1.y); dp[3] = pbf2(v1.z, v1.w);
    }
    for (int i = tid; i < 128 * 8; i += 256) {          // h[pred] -> sH
        int r = i >> 3, seg = (i & 7) * 8;
        int gr = rowBase + r;
        int p = (gr < nrows) ? __ldg(&g_inedge[gr]) : -1;
        float4 v0 = make_float4(0.f,0.f,0.f,0.f), v1 = v0;
        if (p >= 0) {
            const float* sp = (layer == 0) ? emb + (size_t)(__ldg(&items[p]) - 1) * 64
                                           : hin + (size_t)p * 64;
            v0 = *(const float4*)&sp[seg];
            v1 = *(const float4*)&sp[seg + 4];
        }
        uint32_t* dp = (uint32_t*)&sH[r * HKP + seg];
        dp[0] = pbf2(v0.x, v0.y); dp[1] = pbf2(v0.z, v0.w);
        dp[2] = pbf2(v1.x, v1.y); dp[3] = pbf2(v1.z, v1.w);
    }
    for (int i = tid; i < 64 * 8; i += 256) {           // msg weights -> sG
        int c = i >> 3, q = (i & 7) * 8;
        cp16(smem_u32(&sG[c * HKP + q]), &g_msgGb[layer * 4096 + c * 64 + q]);
    }
    asm volatile("cp.async.commit_group;");
    for (int i = tid; i < 154 * 16; i += 256) {         // gruB tail (c>=102: clear of sH/sG)
        int c = 102 + (i >> 4), q = (i & 15) * 8;
        cp16(smem_u32(&sB[c * BKP + q]), &g_gruBb[c * 128 + q]);
    }
    asm volatile("cp.async.commit_group;");
    asm volatile("cp.async.wait_group 1;");
    __syncthreads();

    // ---- phase 1: P = sH @ sG  (warp: 16 rows x 64 cols) ----
    {
        int rowW1 = warp * 16;
        float p[8][4];
#pragma unroll
        for (int nt = 0; nt < 8; nt++)
#pragma unroll
            for (int q = 0; q < 4; q++) p[nt][q] = 0.f;
#pragma unroll
        for (int k0 = 0; k0 < 64; k0 += 16) {
            uint32_t a[4];
            a[0] = *(const uint32_t*)&sH[(rowW1 + lr) * HKP + k0 + 2 * lk];
            a[1] = *(const uint32_t*)&sH[(rowW1 + lr + 8) * HKP + k0 + 2 * lk];
            a[2] = *(const uint32_t*)&sH[(rowW1 + lr) * HKP + k0 + 8 + 2 * lk];
            a[3] = *(const uint32_t*)&sH[(rowW1 + lr + 8) * HKP + k0 + 8 + 2 * lk];
#pragma unroll
            for (int nt = 0; nt < 8; nt++) {
                int c = nt * 8 + lr;
                uint32_t b0 = *(const uint32_t*)&sG[c * HKP + k0 + 2 * lk];
                uint32_t b1 = *(const uint32_t*)&sG[c * HKP + k0 + 8 + 2 * lk];
                mma_bf16(p[nt], a, b0, b1);
            }
        }
#pragma unroll
        for (int nt = 0; nt < 8; nt++) {
            int c0 = nt * 8 + 2 * lk;
            *(uint32_t*)&sA[(rowW1 + lr) * AKP + c0]     = pbf2(p[nt][0], p[nt][1]);
            *(uint32_t*)&sA[(rowW1 + lr + 8) * AKP + c0] = pbf2(p[nt][2], p[nt][3]);
        }
    }
    __syncthreads();
    for (int i = tid; i < 102 * 16; i += 256) {         // gruB head (c<102)
        int c = i >> 4, q = (i & 15) * 8;
        cp16(smem_u32(&sB[c * BKP + q]), &g_gruBb[c * 128 + q]);
    }
    asm volatile("cp.async.commit_group;");
    asm volatile("cp.async.wait_group 0;");
    __syncthreads();

    // ---- phase 2 + epilogue: two 64-row passes (warp: 32 rows x 64 cols) ----
    for (int half = 0; half < 2; half++) {
        int rowW = half * 64 + (warp >> 2) * 32;
        int colW = (warp & 3) * 64;
        float acc[2][8][4];
#pragma unroll
        for (int mt = 0; mt < 2; mt++)
#pragma unroll
            for (int nt = 0; nt < 8; nt++)
#pragma unroll
                for (int q = 0; q < 4; q++) acc[mt][nt][q] = 0.f;

#pragma unroll
        for (int k0 = 0; k0 < 128; k0 += 16) {
            uint32_t a[2][4];
#pragma unroll
            for (int mt = 0; mt < 2; mt++) {
                int r = rowW + mt * 16 + lr;
                a[mt][0] = *(const uint32_t*)&sA[r * AKP + k0 + 2 * lk];
                a[mt][1] = *(const uint32_t*)&sA[(r + 8) * AKP + k0 + 2 * lk];
                a[mt][2] = *(const uint32_t*)&sA[r * AKP + k0 + 8 + 2 * lk];
                a[mt][3] = *(const uint32_t*)&sA[(r + 8) * AKP + k0 + 8 + 2 * lk];
            }
#pragma unroll
            for (int nt = 0; nt < 8; nt++) {
                int c = colW + nt * 8 + lr;
                uint32_t b0 = *(const uint32_t*)&sB[c * BKP + k0 + 2 * lk];
                uint32_t b1 = *(const uint32_t*)&sB[c * BKP + k0 + 8 + 2 * lk];
                mma_bf16(acc[0][nt], a[0], b0, b1);
                mma_bf16(acc[1][nt], a[1], b0, b1);
            }
        }

        int base_j = colW >> 2;
        int odd = lk & 1;
#pragma unroll
        for (int mt = 0; mt < 2; mt++) {
            int r0g = rowBase + rowW + 16 * mt + lr;
            int r1g = r0g + 8;
            const float* hop0 = nullptr;
            const float* hop1 = nullptr;
            if (r0g < nrows)
                hop0 = (layer == 0) ? emb + (size_t)(__ldg(&items[r0g]) - 1) * 64
                                    : hin + (size_t)r0g * 64;
            if (r1g < nrows)
                hop1 = (layer == 0) ? emb + (size_t)(__ldg(&items[r1g]) - 1) * 64
                                    : hin + (size_t)r1g * 64;
#pragma unroll
            for (int nt = 0; nt < 8; nt++) {
                int j = base_j + 2 * nt + ((lk >> 1) & 1);
                float s0 = acc[mt][nt][0], s1 = acc[mt][nt][1];
                float s2 = acc[mt][nt][2], s3 = acc[mt][nt][3];
                float e0 = __shfl_xor_sync(0xffffffffu, s0, 1);
                float e1 = __shfl_xor_sync(0xffffffffu, s1, 1);
                float e2 = __shfl_xor_sync(0xffffffffu, s2, 1);
                float e3 = __shfl_xor_sync(0xffffffffu, s3, 1);
                float xr0 = odd ? e0 : s0, xz0 = odd ? e1 : s1;
                float xi0 = odd ? s0 : e0, xn0 = odd ? s1 : e1;
                float xr1 = odd ? e2 : s2, xz1 = odd ? e3 : s3;
                float xi1 = odd ? s2 : e2, xn1 = odd ? s3 : e3;
                float br = __ldg(&b_ih[j])      + __ldg(&b_hh[j]);
                float bz = __ldg(&b_ih[64 + j]) + __ldg(&b_hh[64 + j]);
                float bi = __ldg(&b_ih[128 + j]);
                float bn = __ldg(&b_hh[128 + j]);
                float ho0 = hop0 ? hop0[j] : 0.f;
                float ho1 = hop1 ? hop1[j] : 0.f;
                float rr0 = fsigmoid(xr0 + br), zz0 = fsigmoid(xz0 + bz);
                float nn0 = ftanh_(fmaf(rr0, xn0 + bn, xi0 + bi));
                float v0 = fmaf(zz0, ho0 - nn0, nn0);
                float rr1 = fsigmoid(xr1 + br), zz1 = fsigmoid(xz1 + bz);
                float nn1 = ftanh_(fmaf(rr1, xn1 + bn, xi1 + bi));
                float v1 = fmaf(zz1, ho1 - nn1, nn1);
                if (do_relu) { v0 = fmaxf(v0, 0.f); v1 = fmaxf(v1, 0.f); }
                float w0 = __shfl_xor_sync(0xffffffffu, v0, 2);
                float w1 = __shfl_xor_sync(0xffffffffu, v1, 2);
                if (lk == 0) {
                    if (r0g < nrows) *(float2*)&hout[r0g * 64 + j] = make_float2(v0, w0);
                    if (r1g < nrows) *(float2*)&hout[r1g * 64 + j] = make_float2(v1, w1);
                }
            }
        }
    }
}

// --------------------- vn_mma: [vnW1 | sh_a] = h[last] @ [W1^T | W3a^T]
#define VN_SMEM ((64 * 68 + 64 * 132) * 4)
__global__ void __launch_bounds__(256) vn_mma(
    const float* __restrict__ W1, const float* __restrict__ W3, int S)
{
    extern __shared__ float vnsm[];
    float* sAt = vnsm;             // [k][row] 64x68
    float* sB  = vnsm + 64 * 68;   // [k][col] 64x132

    int tid = threadIdx.x;
    int rowBase = blockIdx.x * 64;

    for (int i = tid; i < 64 * 64; i += 256) {
        int r = i >> 6, k = i & 63;
        int s = rowBase + r;
        float v = 0.f;
        if (s < S) v = g_hA[(size_t)__ldg(&g_last[s]) * 64 + k];
        sAt[k * 68 + r] = v;
    }
    for (int i = tid; i < 64 * 128; i += 256) {
        int c = i >> 6, k = i & 63;
        float v = (c < 64) ? W1[c * 64 + k] : W3[(c - 64) * 128 + k];
        sB[k * 132 + c] = v;
    }
    __syncthreads();

    int r0 = (tid >> 4) * 4, c0 = (tid & 15) * 8;
    float acc[4][8] = {};
#pragma unroll
    for (int k = 0; k < 64; k++) {
        float4 a = *(const float4*)&sAt[k * 68 + r0];
        float4 bA = *(const float4*)&sB[k * 132 + c0];
        float4 bB = *(const float4*)&sB[k * 132 + c0 + 4];
        float av[4] = {a.x, a.y, a.z, a.w};
        float bv[8] = {bA.x, bA.y, bA.z, bA.w, bB.x, bB.y, bB.z, bB.w};
#pragma unroll
        for (int i = 0; i < 4; i++)
#pragma unroll
            for (int j = 0; j < 8; j++)
                acc[i][j] = fmaf(av[i], bv[j], acc[i][j]);
    }

#pragma unroll
    for (int i = 0; i < 4; i++) {
        int s = rowBase + r0 + i;
        if (s >= S) continue;
        float* outp = (c0 < 64) ? &g_vnW1[s * 64 + c0] : &g_sh[s * 64 + (c0 - 64)];
        *(float4*)outp       = make_float4(acc[i][0], acc[i][1], acc[i][2], acc[i][3]);
        *(float4*)(outp + 4) = make_float4(acc[i][4], acc[i][5], acc[i][6], acc[i][7]);
    }
}

// ------------------------- bf16 mma: hW2 + register gate epilogue
#define W2_SMEM ((128 * 72 + 64 * 72) * 2)
__global__ void __launch_bounds__(256) w2gate_mma(
    const int* __restrict__ batch,
    const float* __restrict__ bb1, const float* __restrict__ bb2,
    const float* __restrict__ qw, const float* __restrict__ qb,
    int nrows)
{
    extern __shared__ uint16_t smw[];
    uint16_t* sA = smw;               // [128][72]
    uint16_t* sB = smw + 128 * 72;    // [64][72]

    int tid = threadIdx.x;
    int lane = tid & 31;
    int warp = tid >> 5;
    int lr = lane >> 2, lk = lane & 3;
    int rowBase = blockIdx.x * 128;

    for (int i = tid; i < 128 * 8; i += 256) {
        int r = i >> 3, seg = (i & 7) * 8;
        int gr = rowBase + r;
        float4 v0 = make_float4(0.f,0.f,0.f,0.f), v1 = v0;
        if (gr < nrows) {
            v0 = *(const float4*)&g_hA[gr * 64 + seg];
            v1 = *(const float4*)&g_hA[gr * 64 + seg + 4];
        }
        uint32_t* dp = (uint32_t*)&sA[r * 72 + seg];
        dp[0] = pbf2(v0.x, v0.y); dp[1] = pbf2(v0.z, v0.w);
        dp[2] = pbf2(v1.x, v1.y); dp[3] = pbf2(v1.z, v1.w);
    }
    for (int i = tid; i < 64 * 8; i += 256) {
        int c = i >> 3, q = (i & 7) * 8;
        cp16(smem_u32(&sB[c * 72 + q]), &g_w2Bb[c * 64 + q]);
    }
    asm volatile("cp.async.commit_group;");
    asm volatile("cp.async.wait_group 0;");
    __syncthreads();

    int rowW = warp * 16;
    float acc[8][4];
#pragma unroll
    for (int nt = 0; nt < 8; nt++)
#pragma unroll
        for (int q = 0; q < 4; q++) acc[nt][q] = 0.f;

#pragma unroll
    for (int k0 = 0; k0 < 64; k0 += 16) {
        uint32_t a[4];
        a[0] = *(const uint32_t*)&sA[(rowW + lr) * 72 + k0 + 2 * lk];
        a[1] = *(const uint32_t*)&sA[(rowW + lr + 8) * 72 + k0 + 2 * lk];
        a[2] = *(const uint32_t*)&sA[(rowW + lr) * 72 + k0 + 8 + 2 * lk];
        a[3] = *(const uint32_t*)&sA[(rowW + lr + 8) * 72 + k0 + 8 + 2 * lk];
#pragma unroll
        for (int nt = 0; nt < 8; nt++) {
            int c = nt * 8 + lr;
            uint32_t b0 = *(const uint32_t*)&sB[c * 72 + k0 + 2 * lk];
            uint32_t b1 = *(const uint32_t*)&sB[c * 72 + k0 + 8 + 2 * lk];
            mma_bf16(acc[nt], a, b0, b1);
        }
    }

    // register epilogue: rows r0g (=..+lr), r1g (=+8)
    int r0g = rowBase + rowW + lr;
    int r1g = r0g + 8;
    int bs0 = (r0g < nrows) ? __ldg(&batch[r0g]) : 0;
    int bs1 = (r1g < nrows) ? __ldg(&batch[r1g]) : 0;
    float al0 = 0.f, al1 = 0.f;
#pragma unroll
    for (int nt = 0; nt < 8; nt++) {
#pragma unroll
        for (int q = 0; q < 2; q++) {
            int c = nt * 8 + 2 * lk + q;
            float bias = __ldg(&bb1[c]) + __ldg(&bb2[c]);
            float qv = __ldg(&qw[c]);
            float x0 = acc[nt][q]     + g_vnW1[bs0 * 64 + c] + bias;
            float x1 = acc[nt][2 + q] + g_vnW1[bs1 * 64 + c] + bias;
            al0 = fmaf(fsigmoid(x0), qv, al0);
            al1 = fmaf(fsigmoid(x1), qv, al1);
        }
    }
    al0 += __shfl_xor_sync(0xffffffffu, al0, 1);
    al0 += __shfl_xor_sync(0xffffffffu, al0, 2);
    al1 += __shfl_xor_sync(0xffffffffu, al1, 1);
    al1 += __shfl_xor_sync(0xffffffffu, al1, 2);
    float qbv = __ldg(&qb[0]);
    al0 += qbv; al1 += qbv;
#pragma unroll
    for (int nt = 0; nt < 8; nt++) {
#pragma unroll
        for (int q = 0; q < 2; q++) {
            int c = nt * 8 + 2 * lk + q;
            if (r0g < nrows) atomicAdd(&g_sg[bs0 * 64 + c], al0 * g_hA[r0g * 64 + c]);
            if (r1g < nrows) atomicAdd(&g_sg[bs1 * 64 + c], al1 * g_hA[r1g * 64 + c]);
        }
    }
}

// --------------------- final accum: g_sh += g_sg @ W3b^T + b3
__global__ void __launch_bounds__(256) shb_gemm(
    const float* __restrict__ W3, const float* __restrict__ b3, int S)
{
    __shared__ float sAt[64][68];
    __shared__ float sB [64][68];
    int tid = threadIdx.x;
    int rowBase = blockIdx.x * 64;

    for (int i = tid; i < 64 * 64; i += 256) {
        int r = i >> 6, k = i & 63;
        int s = rowBase + r;
        sAt[k][r] = (s < S) ? g_sg[s * 64 + k] : 0.f;
    }
    for (int i = tid; i < 64 * 64; i += 256) {
        int j = i >> 6, k = i & 63;
        sB[k][j] = W3[j * 128 + 64 + k];
    }
    __syncthreads();

    int r0 = (tid >> 4) * 4, c0 = (tid & 15) * 4;
    float acc[4][4] = {};
#pragma unroll
    for (int k = 0; k < 64; k++) {
        float4 a = *(const float4*)&sAt[k][r0];
        float4 b = *(const float4*)&sB[k][c0];
        float av[4] = {a.x, a.y, a.z, a.w};
        float bv[4] = {b.x, b.y, b.z, b.w};
#pragma unroll
        for (int i = 0; i < 4; i++)
#pragma unroll
            for (int j = 0; j < 4; j++)
                acc[i][j] = fmaf(av[i], bv[j], acc[i][j]);
    }

    float4 bb = make_float4(b3[c0], b3[c0+1], b3[c0+2], b3[c0+3]);
#pragma unroll
    for (int i = 0; i < 4; i++) {
        int s = rowBase + r0 + i;
        if (s < S) {
            float* cp = &g_sh[s * 64 + c0];
            float4 p = *(const float4*)cp;
            *(float4*)cp = make_float4(acc[i][0] + bb.x + p.x, acc[i][1] + bb.y + p.y,
                                       acc[i][2] + bb.z + p.z, acc[i][3] + bb.w + p.w);
        }
    }
}

// ------------------------------------------------------------ BPR loss
__global__ void loss_kernel(const float* __restrict__ item_emb,
                            const int* __restrict__ pos, const int* __restrict__ neg,
                            int S)
{
    int gidx = blockIdx.x * blockDim.x + threadIdx.x;
    int s = gidx >> 5;
    if (s >= S) return;
    int lane = gidx & 31;
    int ip = pos[s], in2 = neg[s];
    float pp = 0.f, np = 0.f, rg = 0.f;
#pragma unroll
    for (int t = 0; t < 2; t++) {
        int j = lane + t * 32;
        float sv = g_sh[s * 64 + j];
        float pe = item_emb[ip * 64 + j];
        float ne = item_emb[in2 * 64 + j];
        pp = fmaf(sv, pe, pp);
        np = fmaf(sv, ne, np);
        rg += sv * sv + pe * pe + ne * ne;
    }
#pragma unroll
    for (int o = 16; o; o >>= 1) {
        pp += __shfl_xor_sync(0xffffffffu, pp, o);
        np += __shfl_xor_sync(0xffffffffu, np, o);
        rg += __shfl_xor_sync(0xffffffffu, rg, o);
    }
    if (lane == 0) {
        float x = pp - np;
        float lsm = (x > 0.f) ? log1pf(expf(-x)) : (-x + log1pf(expf(x)));
        atomicAdd(&g_acc[0], (double)lsm);
        atomicAdd(&g_acc[1], (double)rg);
    }
}

__global__ void finalize_kernel(float* out, int out_size)
{
    double loss = g_acc[0];
    double nr = g_acc[1] * 1e-5;
    float t = (float)(loss + nr), l = (float)loss, r = (float)nr;
    if (out_size > 0) out[0] = t;
    if (out_size > 1) out[1] = l;
    if (out_size > 2) out[2] = r;
    if (out_size > 3) out[3] = r;
    if (out_size > 4) out[4] = r;
}

// ---------------------------------------------------------------- host
extern "C" void kernel_launch(void* const* d_in, const int* in_sizes, int n_in,
                              void* d_out, int out_size)
{
    const float* item_emb = (const float*)d_in[0];
    const float* ggc      = (const float*)d_in[1];
    const float* W_ih     = (const float*)d_in[2];
    const float* b_ih     = (const float*)d_in[3];
    const float* W_hh     = (const float*)d_in[4];
    const float* b_hh     = (const float*)d_in[5];
    const float* W1       = (const float*)d_in[6];
    const float* b1       = (const float*)d_in[7];
    const float* W2       = (const float*)d_in[8];
    const float* b2       = (const float*)d_in[9];
    const float* qw       = (const float*)d_in[10];
    const float* qb       = (const float*)d_in[11];
    const float* W3       = (const float*)d_in[12];
    const float* b3       = (const float*)d_in[13];
    const int* node_items = (const int*)d_in[14];
    const int* edge_index = (const int*)d_in[15];
    const int* batch      = (const int*)d_in[16];
    const int* pos        = (const int*)d_in[17];
    const int* neg        = (const int*)d_in[18];

    int N = in_sizes[14];
    int E = in_sizes[15] / 2;
    int S = in_sizes[17];
    float* out = (float*)d_out;

    cudaFuncSetAttribute(gru_fused,  cudaFuncAttributeMaxDynamicSharedMemorySize, GRUF_SMEM);
    cudaFuncSetAttribute(w2gate_mma, cudaFuncAttributeMaxDynamicSharedMemorySize, W2_SMEM);
    cudaFuncSetAttribute(vn_mma,     cudaFuncAttributeMaxDynamicSharedMemorySize, VN_SMEM);

    const int* src = edge_index;
    const int* dst = edge_index + E;
    int gTiles = (N + 127) / 128;
    int initCnt = (N > S * D) ? N : S * D;

    prepack_kernel<<<(256 * 128 + 3 * 4096 + 255) / 256, 256>>>(W_ih, W_hh, ggc, W2);
    zero_misc_kernel<<<(initCnt + 255) / 256, 256>>>(S, N);
    build_inedge_kernel<<<(E + 255) / 256, 256>>>(src, dst, E);
    lastmax_kernel<<<(N + 255) / 256, 256>>>(batch, N);

    // layer 0: emb -> g_hB ; layer 1: g_hB -> g_hA (+relu)
    gru_fused<<<gTiles, 256, GRUF_SMEM>>>(0, b_ih, b_hh, N, 0, 0, item_emb, node_items);
    gru_fused<<<gTiles, 256, GRUF_SMEM>>>(1, b_ih, b_hh, N, 1, 1, item_emb, node_items);

    vn_mma<<<(S + 63) / 64, 256, VN_SMEM>>>(W1, W3, S);
    w2gate_mma<<<gTiles, 256, W2_SMEM>>>(batch, b1, b2, qw, qb, N);
    shb_gemm<<<(S + 63) / 64, 256>>>(W3, b3, S);

    loss_kernel<<<(S * 32 + 255) / 256, 256>>>(item_emb, pos, neg, S);
    finalize_kernel<<<1, 1>>>(out, out_size);
}